// round 11
// baseline (speedup 1.0000x reference)
#include <cuda_runtime.h>
#include <math.h>

// Problem constants
#define Dm   512
#define Hn   8
#define DKn  64
#define Sn   512
#define Bn   4
#define NTOK 2048      // B * S
#define DFFn 2048
#define Vn   32000
#define LEn  6
#define LDn  6

typedef long long ll;

// -------------------- scratch (device globals; no allocation) --------------------
__device__ float g_x   [NTOK * Dm];       // fp32 residual stream (encoder)
__device__ float g_y   [NTOK * Dm];       // fp32 residual stream (decoder)
__device__ float g_xr  [NTOK * Dm];       // tf32-rounded copy of g_x
__device__ float g_yr  [NTOK * Dm];       // tf32-rounded copy of g_y
__device__ float g_qkv [3 * NTOK * Dm];   // rounded
__device__ float g_ctx [NTOK * Dm];       // rounded (flash epilogue)
__device__ float g_part[4 * NTOK * Dm];   // split-K partials (raw fp32)
__device__ float g_ffn [NTOK * DFFn];     // rounded (ffn1 epilogue)

// tf32-rounded weight copies (wO handled in-kernel by final GEMM)
__device__ float g_wEA [LEn * 4 * Dm * Dm];
__device__ float g_wEF1[LEn * Dm * DFFn];
__device__ float g_wEF2[LEn * DFFn * Dm];
__device__ float g_wDS [LDn * 4 * Dm * Dm];
__device__ float g_wDC [LDn * 4 * Dm * Dm];
__device__ float g_wDF1[LDn * Dm * DFFn];
__device__ float g_wDF2[LDn * DFFn * Dm];

// -------------------- helpers --------------------
__device__ __forceinline__ float to_tf32(float x) {
    float y;
    asm("cvt.rna.tf32.f32 %0, %1;" : "=f"(y) : "f"(x));
    return y;
}

__device__ __forceinline__ void mma_tf32(float* d, const unsigned* a, const unsigned* b) {
    asm volatile(
        "mma.sync.aligned.m16n8k8.row.col.f32.tf32.tf32.f32 "
        "{%0,%1,%2,%3}, {%4,%5,%6,%7}, {%8,%9}, {%0,%1,%2,%3};\n"
        : "+f"(d[0]), "+f"(d[1]), "+f"(d[2]), "+f"(d[3])
        : "r"(a[0]), "r"(a[1]), "r"(a[2]), "r"(a[3]), "r"(b[0]), "r"(b[1]));
}

__device__ __forceinline__ unsigned su32(const void* p) {
    return (unsigned)__cvta_generic_to_shared(p);
}
#define CP_ASYNC16(s, g) \
    asm volatile("cp.async.cg.shared.global [%0], [%1], 16;\n" :: "r"(s), "l"(g))
#define CP_COMMIT() asm volatile("cp.async.commit_group;\n" ::: "memory")

// -------------------- tf32 pre-round (weights) --------------------
__global__ void cvt_k(const float* __restrict__ in, float* __restrict__ out, int n4) {
    int i = blockIdx.x * 256 + threadIdx.x;
    if (i < n4) {
        float4 v = ((const float4*)in)[i];
        v.x = to_tf32(v.x); v.y = to_tf32(v.y);
        v.z = to_tf32(v.z); v.w = to_tf32(v.w);
        ((float4*)out)[i] = v;
    }
}

// ==================== TF32 multistage tensor-core GEMM ====================
// Operands pre-rounded to tf32 unless CVTB (B rounded at fragment load).
template<int BM, int BN, int BK, int WGM, int WGN, int NTH, int STAGES,
         bool RELU, bool ROUND, bool CVTB>
__global__ void __launch_bounds__(NTH)
gemm_tc(const float* __restrict__ A, const float* __restrict__ Aalt,
        const float* __restrict__ B, float* __restrict__ C,
        const float* __restrict__ bias,
        int K, int lda, int ldb, int ldc,
        ll sAz, ll sBz, ll sCz, int biasStride, int biasZ0) {
    const int z = blockIdx.z;
    if (Aalt != nullptr && z > 0) A = Aalt;
    A += (ll)z * sAz;
    B += (ll)z * sBz;
    C += (ll)z * sCz;
    if (bias) {
        if (biasZ0 && z > 0) bias = nullptr;
        else bias += (ll)z * biasStride;
    }

    const int tid = threadIdx.x;
    const int lane = tid & 31, warp = tid >> 5;
    const int wm = warp / WGN, wn = warp % WGN;
    constexpr int WTM = BM / WGM, WTN = BN / WGN;
    constexpr int MT = WTM / 16, NT = WTN / 8;
    const int row0 = blockIdx.y * BM, col0 = blockIdx.x * BN;
    const int g = lane >> 2, tg = lane & 3;

    extern __shared__ float smem[];
    constexpr int AL = BK + 4;
    constexpr int BL = BN + 8;
    constexpr int ASZ = BM * AL;
    constexpr int BSZ = BK * BL;
    float* Asm = smem;
    float* Bsm = smem + STAGES * ASZ;

    constexpr int CA = BM * BK / (4 * NTH);
    constexpr int CB = BK * BN / (4 * NTH);

    auto issue = [&](int it, int st) {
        const int k0 = it * BK;
        float* as = Asm + st * ASZ;
        float* bs = Bsm + st * BSZ;
#pragma unroll
        for (int i = 0; i < CA; i++) {
            int t = tid + i * NTH;
            int r = t / (BK / 4), kq = (t % (BK / 4)) * 4;
            CP_ASYNC16(su32(as + r * AL + kq), A + (ll)(row0 + r) * lda + k0 + kq);
        }
#pragma unroll
        for (int i = 0; i < CB; i++) {
            int t = tid + i * NTH;
            int r = t / (BN / 4), nq = (t % (BN / 4)) * 4;
            CP_ASYNC16(su32(bs + r * BL + nq), B + (ll)(k0 + r) * ldb + col0 + nq);
        }
        CP_COMMIT();
    };

    float acc[MT][NT][4] = {};
    const int nIt = K / BK;

#pragma unroll
    for (int s = 0; s < STAGES - 1; s++)
        if (s < nIt) issue(s, s);

    for (int it = 0; it < nIt; it++) {
        asm volatile("cp.async.wait_group %0;\n" :: "n"(STAGES - 2) : "memory");
        __syncthreads();
        const int pre = it + STAGES - 1;
        if (pre < nIt) issue(pre, pre % STAGES);
        else CP_COMMIT();

        const float* as = Asm + (it % STAGES) * ASZ;
        const float* bs = Bsm + (it % STAGES) * BSZ;

#pragma unroll
        for (int ks = 0; ks < BK / 8; ks++) {
            const int kb = ks * 8;
            unsigned af[MT][4], bf[NT][2];
#pragma unroll
            for (int mt = 0; mt < MT; mt++) {
                int r = wm * WTM + mt * 16 + g;
                af[mt][0] = __float_as_uint(as[r * AL + kb + tg]);
                af[mt][1] = __float_as_uint(as[(r + 8) * AL + kb + tg]);
                af[mt][2] = __float_as_uint(as[r * AL + kb + tg + 4]);
                af[mt][3] = __float_as_uint(as[(r + 8) * AL + kb + tg + 4]);
            }
#pragma unroll
            for (int nt = 0; nt < NT; nt++) {
                int c = wn * WTN + nt * 8 + g;
                if (CVTB) {
                    bf[nt][0] = __float_as_uint(to_tf32(bs[(kb + tg) * BL + c]));
                    bf[nt][1] = __float_as_uint(to_tf32(bs[(kb + tg + 4) * BL + c]));
                } else {
                    bf[nt][0] = __float_as_uint(bs[(kb + tg) * BL + c]);
                    bf[nt][1] = __float_as_uint(bs[(kb + tg + 4) * BL + c]);
                }
            }
#pragma unroll
            for (int mt = 0; mt < MT; mt++)
#pragma unroll
                for (int nt = 0; nt < NT; nt++)
                    mma_tf32(acc[mt][nt], af[mt], bf[nt]);
        }
    }

#pragma unroll
    for (int mt = 0; mt < MT; mt++) {
#pragma unroll
        for (int nt = 0; nt < NT; nt++) {
            int r = row0 + wm * WTM + mt * 16 + g;
            int c = col0 + wn * WTN + nt * 8 + tg * 2;
            float b0 = 0.f, b1 = 0.f;
            if (bias) { b0 = bias[c]; b1 = bias[c + 1]; }
            float2 v0, v1;
            v0.x = acc[mt][nt][0] + b0; v0.y = acc[mt][nt][1] + b1;
            v1.x = acc[mt][nt][2] + b0; v1.y = acc[mt][nt][3] + b1;
            if (RELU) {
                v0.x = fmaxf(v0.x, 0.f); v0.y = fmaxf(v0.y, 0.f);
                v1.x = fmaxf(v1.x, 0.f); v1.y = fmaxf(v1.y, 0.f);
            }
            if (ROUND) {
                v0.x = to_tf32(v0.x); v0.y = to_tf32(v0.y);
                v1.x = to_tf32(v1.x); v1.y = to_tf32(v1.y);
            }
            *(float2*)(C + (ll)r * ldc + c) = v0;
            *(float2*)(C + (ll)(r + 8) * ldc + c) = v1;
        }
    }
}

// ==================== fused flash attention ====================
// Q in registers (A-fragments). K double-buffered, V single-buffered via cp.async.
// smem: K[2] + V + P = 4 tiles (~70KB) -> 3 blocks/SM.
// Causal mode processes only tiles kt <= qt (skipped tiles contribute exactly 0);
// fully-masked rows (tok==0) are corrected by fix_k afterwards.
#define FA_STRIDE 68
#define FA_TILE (64 * FA_STRIDE)
__global__ void __launch_bounds__(128)
flash_k(const float* __restrict__ Q, const float* __restrict__ Kv,
        const float* __restrict__ Vv, float* __restrict__ ctx,
        const int* __restrict__ tok, int causal) {
    extern __shared__ float sm[];
    float* Ks = sm;                     // [2][64][68]
    float* Vs = sm + 2 * FA_TILE;       // [64][68]
    float* Ps = sm + 3 * FA_TILE;       // [64][68]
    int* kmv = (int*)(sm + 4 * FA_TILE);

    const int qt = blockIdx.x, h = blockIdx.y, b = blockIdx.z;
    const int tid = threadIdx.x, lane = tid & 31, w = tid >> 5;
    const int g = lane >> 2, tg = lane & 3;
    const int wrow = w * 16;

    const ll base = (ll)(b * Sn) * Dm + h * DKn;
    const int kp = tid >> 1, half = (tid & 1) * 32;
    const int ktiles = causal ? (qt + 1) : 8;

    auto issueK = [&](int kt, int buf) {
        const float* ksrc = Kv + base + (ll)(kt * 64 + kp) * Dm + half;
        unsigned kdst = su32(Ks + buf * FA_TILE + kp * FA_STRIDE + half);
#pragma unroll
        for (int j = 0; j < 32; j += 4) CP_ASYNC16(kdst + j * 4, ksrc + j);
        CP_COMMIT();
    };
    auto issueV = [&](int kt) {
        const float* vsrc = Vv + base + (ll)(kt * 64 + kp) * Dm + half;
        unsigned vdst = su32(Vs + kp * FA_STRIDE + half);
#pragma unroll
        for (int j = 0; j < 32; j += 4) CP_ASYNC16(vdst + j * 4, vsrc + j);
        CP_COMMIT();
    };

    // K0 + stage Q (through Vs) in flight together
    issueK(0, 0);
    {
        const float* qsrc = Q + base + (ll)(qt * 64 + kp) * Dm + half;
        unsigned qdst = su32(Vs + kp * FA_STRIDE + half);
#pragma unroll
        for (int j = 0; j < 32; j += 4) CP_ASYNC16(qdst + j * 4, qsrc + j);
        CP_COMMIT();
    }
    asm volatile("cp.async.wait_group 0;\n" ::: "memory");
    __syncthreads();

    // Q fragments -> registers
    unsigned qf[8][4];
#pragma unroll
    for (int kc = 0; kc < 8; kc++) {
        const int kb = kc * 8;
        qf[kc][0] = __float_as_uint(Vs[(wrow + g) * FA_STRIDE + kb + tg]);
        qf[kc][1] = __float_as_uint(Vs[(wrow + g + 8) * FA_STRIDE + kb + tg]);
        qf[kc][2] = __float_as_uint(Vs[(wrow + g) * FA_STRIDE + kb + tg + 4]);
        qf[kc][3] = __float_as_uint(Vs[(wrow + g + 8) * FA_STRIDE + kb + tg + 4]);
    }
    __syncthreads();
    issueV(0);

    const int qrow0 = qt * 64 + wrow + g, qrow1 = qrow0 + 8;
    float m0 = -1e30f, m1 = -1e30f, l0 = 0.f, l1 = 0.f;
    float acc_o[8][4] = {};

    for (int kt = 0; kt < ktiles; kt++) {
        const int buf = kt & 1;
        if (!causal && tid < 64) kmv[tid] = tok[b * Sn + kt * 64 + tid];
        if (kt + 1 < ktiles) issueK(kt + 1, buf ^ 1);
        else CP_COMMIT();
        // in flight: ..., V(kt), K(kt+1). wait all but newest -> K(kt),V(kt) done.
        asm volatile("cp.async.wait_group 1;\n" ::: "memory");
        __syncthreads();

        const float* Kb = Ks + buf * FA_TILE;

        float s[8][4] = {};
#pragma unroll
        for (int kc = 0; kc < 8; kc++) {
            const int kb = kc * 8;
#pragma unroll
            for (int nt = 0; nt < 8; nt++) {
                unsigned bf[2];
                bf[0] = __float_as_uint(Kb[(nt * 8 + g) * FA_STRIDE + kb + tg]);
                bf[1] = __float_as_uint(Kb[(nt * 8 + g) * FA_STRIDE + kb + tg + 4]);
                mma_tf32(s[nt], qf[kc], bf);
            }
        }

        float vmax0 = -1e30f, vmax1 = -1e30f;
#pragma unroll
        for (int nt = 0; nt < 8; nt++) {
#pragma unroll
            for (int jj = 0; jj < 2; jj++) {
                int ncol = nt * 8 + tg * 2 + jj;
                int kcol = kt * 64 + ncol;
                bool mk0, mk1;
                if (causal) { mk0 = (kcol <= qrow0); mk1 = (kcol <= qrow1); }
                else        { bool km = kmv[ncol] != 0; mk0 = km; mk1 = km; }
                float v0 = mk0 ? s[nt][jj] * 0.125f : -1e9f;
                float v1 = mk1 ? s[nt][2 + jj] * 0.125f : -1e9f;
                s[nt][jj] = v0; s[nt][2 + jj] = v1;
                vmax0 = fmaxf(vmax0, v0); vmax1 = fmaxf(vmax1, v1);
            }
        }
        vmax0 = fmaxf(vmax0, __shfl_xor_sync(0xffffffffu, vmax0, 1));
        vmax0 = fmaxf(vmax0, __shfl_xor_sync(0xffffffffu, vmax0, 2));
        vmax1 = fmaxf(vmax1, __shfl_xor_sync(0xffffffffu, vmax1, 1));
        vmax1 = fmaxf(vmax1, __shfl_xor_sync(0xffffffffu, vmax1, 2));

        float mn0 = fmaxf(m0, vmax0), mn1 = fmaxf(m1, vmax1);
        float a0 = __expf(m0 - mn0), a1 = __expf(m1 - mn1);
        m0 = mn0; m1 = mn1;

        float rs0 = 0.f, rs1 = 0.f;
#pragma unroll
        for (int nt = 0; nt < 8; nt++) {
#pragma unroll
            for (int jj = 0; jj < 2; jj++) {
                int ncol = nt * 8 + tg * 2 + jj;
                float p0 = __expf(s[nt][jj] - mn0);
                float p1 = __expf(s[nt][2 + jj] - mn1);
                rs0 += p0; rs1 += p1;
                Ps[(wrow + g) * FA_STRIDE + ncol] = to_tf32(p0);
                Ps[(wrow + g + 8) * FA_STRIDE + ncol] = to_tf32(p1);
            }
        }
        rs0 += __shfl_xor_sync(0xffffffffu, rs0, 1);
        rs0 += __shfl_xor_sync(0xffffffffu, rs0, 2);
        rs1 += __shfl_xor_sync(0xffffffffu, rs1, 1);
        rs1 += __shfl_xor_sync(0xffffffffu, rs1, 2);
        l0 = l0 * a0 + rs0; l1 = l1 * a1 + rs1;
#pragma unroll
        for (int nt = 0; nt < 8; nt++) {
            acc_o[nt][0] *= a0; acc_o[nt][1] *= a0;
            acc_o[nt][2] *= a1; acc_o[nt][3] *= a1;
        }
        __syncwarp();

#pragma unroll
        for (int kc = 0; kc < 8; kc++) {
            const int kb = kc * 8;
            unsigned af[4];
            af[0] = __float_as_uint(Ps[(wrow + g) * FA_STRIDE + kb + tg]);
            af[1] = __float_as_uint(Ps[(wrow + g + 8) * FA_STRIDE + kb + tg]);
            af[2] = __float_as_uint(Ps[(wrow + g) * FA_STRIDE + kb + tg + 4]);
            af[3] = __float_as_uint(Ps[(wrow + g + 8) * FA_STRIDE + kb + tg + 4]);
#pragma unroll
            for (int nt = 0; nt < 8; nt++) {
                unsigned bf[2];
                bf[0] = __float_as_uint(Vs[(kb + tg) * FA_STRIDE + nt * 8 + g]);
                bf[1] = __float_as_uint(Vs[(kb + tg + 4) * FA_STRIDE + nt * 8 + g]);
                mma_tf32(acc_o[nt], af, bf);
            }
        }
        __syncthreads();   // done reading Vs/Ps/kmv
        if (kt + 1 < ktiles) issueV(kt + 1);
        else CP_COMMIT();
    }

    float inv0 = 1.f / l0, inv1 = 1.f / l1;
#pragma unroll
    for (int nt = 0; nt < 8; nt++) {
        int c = nt * 8 + tg * 2;
        float2 o0, o1;
        o0.x = to_tf32(acc_o[nt][0] * inv0); o0.y = to_tf32(acc_o[nt][1] * inv0);
        o1.x = to_tf32(acc_o[nt][2] * inv1); o1.y = to_tf32(acc_o[nt][3] * inv1);
        *(float2*)(ctx + base + (ll)qrow0 * Dm + c) = o0;
        *(float2*)(ctx + base + (ll)qrow1 * Dm + c) = o1;
    }
}

// -------------------- causal fully-masked-row fixup --------------------
// For rows with tok==0 (softmax uniform over all Sn keys): ctx = mean(V).
__global__ void fix_k(const float* __restrict__ Vv, float* __restrict__ ctx,
                      const int* __restrict__ tok) {
    int h = blockIdx.x & (Hn - 1), b = blockIdx.x / Hn;
    int d = threadIdx.x;   // 64
    // early exit if no zero token in this batch row
    __shared__ int hasz;
    if (d == 0) hasz = 0;
    __syncthreads();
    for (int q = d; q < Sn; q += 64)
        if (tok[b * Sn + q] == 0) atomicOr(&hasz, 1);
    __syncthreads();
    if (!hasz) return;

    const ll base = (ll)(b * Sn) * Dm + h * DKn;
    float s = 0.f;
    for (int k = 0; k < Sn; k++) s += Vv[base + (ll)k * Dm + d];
    s = to_tf32(s * (1.0f / Sn));
    for (int q = 0; q < Sn; q++)
        if (tok[b * Sn + q] == 0) ctx[base + (ll)q * Dm + d] = s;
}

// -------------------- embedding + PE (dual write: fp32 + tf32) --------------------
__global__ void embed_k(float* __restrict__ out, float* __restrict__ outr,
                        const float* __restrict__ emb,
                        const int* __restrict__ tok, const float* __restrict__ pe) {
    int t = blockIdx.x;
    int s = t & (Sn - 1);
    int tk = tok[t];
    const float scale = 22.627416997969522f;
    int base = t * Dm;
    for (int d = threadIdx.x; d < Dm; d += blockDim.x) {
        float v = emb[tk * Dm + d] * scale + pe[s * Dm + d];
        out[base + d] = v;
        outr[base + d] = to_tf32(v);
    }
}

// -------------------- residual + split-K reduce + LayerNorm (dual write) --------------------
__global__ void ln_res_k(float* __restrict__ x, float* __restrict__ xr,
                         const float* __restrict__ parts, int npart, ll pstride,
                         const float* __restrict__ g, const float* __restrict__ be) {
    int r = blockIdx.x;
    int base = r * Dm;
    int tid = threadIdx.x;
    float v0 = x[base + tid];
    float v1 = x[base + tid + 256];
    for (int p = 0; p < npart; p++) {
        v0 += parts[p * pstride + base + tid];
        v1 += parts[p * pstride + base + tid + 256];
    }

    float s = v0 + v1;
    float sq = v0 * v0 + v1 * v1;
    __shared__ float rs[8], rq[8];
#pragma unroll
    for (int o = 16; o; o >>= 1) {
        s  += __shfl_xor_sync(0xffffffffu, s, o);
        sq += __shfl_xor_sync(0xffffffffu, sq, o);
    }
    if ((tid & 31) == 0) { rs[tid >> 5] = s; rq[tid >> 5] = sq; }
    __syncthreads();
    if (tid < 8) {
        float a1 = rs[tid], a2 = rq[tid];
#pragma unroll
        for (int o = 4; o; o >>= 1) {
            a1 += __shfl_xor_sync(0xffu, a1, o);
            a2 += __shfl_xor_sync(0xffu, a2, o);
        }
        if (tid == 0) { rs[0] = a1; rq[0] = a2; }
    }
    __syncthreads();
    float mu = rs[0] * (1.0f / Dm);
    float var = rq[0] * (1.0f / Dm) - mu * mu;
    float inv = rsqrtf(var + 1e-5f);
    float o0 = g[tid]       * (v0 - mu) * inv + be[tid];
    float o1 = g[tid + 256] * (v1 - mu) * inv + be[tid + 256];
    x[base + tid]        = o0;
    x[base + tid + 256]  = o1;
    xr[base + tid]       = to_tf32(o0);
    xr[base + tid + 256] = to_tf32(o1);
}

// ==================== host orchestration ====================
#define STG 3
static inline int smemBytes(int BM, int BN, int BK) {
    return STG * (BM * (BK + 4) + BK * (BN + 8)) * 4;
}

static void CVT(const float* in, float* out, ll n) {
    int n4 = (int)(n / 4);
    cvt_k<<<(n4 + 255) / 256, 256>>>(in, out, n4);
}

template<bool RELU, bool ROUND, bool CVTB>
static void NN_big(const float* A, const float* B, float* C, const float* bias,
                   int M, int N, int K) {
    dim3 grid(N / 128, M / 128, 1);
    int sb = smemBytes(128, 128, 32);
    cudaFuncSetAttribute((const void*)gemm_tc<128, 128, 32, 2, 4, 256, STG, RELU, ROUND, CVTB>,
                         cudaFuncAttributeMaxDynamicSharedMemorySize, sb);
    gemm_tc<128, 128, 32, 2, 4, 256, STG, RELU, ROUND, CVTB><<<grid, 256, sb>>>(
        A, nullptr, B, C, bias, K, K, N, N, 0, 0, 0, 0, 0);
}

static void NN_512_split(const float* A, const float* B, float* Cpart,
                         const float* bias, int K, int nsplit) {
    int Ksl = K / nsplit;
    dim3 grid(Dm / 64, NTOK / 64, nsplit);
    int sb = smemBytes(64, 64, 32);
    cudaFuncSetAttribute((const void*)gemm_tc<64, 64, 32, 2, 2, 128, STG, false, false, false>,
                         cudaFuncAttributeMaxDynamicSharedMemorySize, sb);
    gemm_tc<64, 64, 32, 2, 2, 128, STG, false, false, false><<<grid, 128, sb>>>(
        A, nullptr, B, Cpart, bias, Ksl, K, Dm, Dm,
        (ll)Ksl, (ll)Ksl * Dm, (ll)NTOK * Dm, 0, 1);
}

static void QKV(const float* xq, const float* xkv, const float* w4, const float* b4,
                float* qkv) {
    dim3 grid(Dm / 64, NTOK / 64, 3);
    int sb = smemBytes(64, 64, 32);
    cudaFuncSetAttribute((const void*)gemm_tc<64, 64, 32, 2, 2, 128, STG, false, true, false>,
                         cudaFuncAttributeMaxDynamicSharedMemorySize, sb);
    gemm_tc<64, 64, 32, 2, 2, 128, STG, false, true, false><<<grid, 128, sb>>>(
        xq, xkv, w4, qkv, b4, Dm, Dm, Dm, Dm,
        0, (ll)Dm * Dm, (ll)NTOK * Dm, Dm, 0);
}

static const int FA_SMEM = (4 * FA_TILE) * 4 + 256;
static const ll PSTRIDE = (ll)NTOK * Dm;

extern "C" void kernel_launch(void* const* d_in, const int* in_sizes, int n_in,
                              void* d_out, int out_size) {
    const int*   src        = (const int*)  d_in[0];
    const int*   tgt        = (const int*)  d_in[1];
    const float* enc_emb    = (const float*)d_in[2];
    const float* dec_emb    = (const float*)d_in[3];
    const float* pe         = (const float*)d_in[4];
    const float* enc_attn_w = (const float*)d_in[5];
    const float* enc_attn_b = (const float*)d_in[6];
    const float* enc_ffn_w1 = (const float*)d_in[7];
    const float* enc_ffn_b1 = (const float*)d_in[8];
    const float* enc_ffn_w2 = (const float*)d_in[9];
    const float* enc_ffn_b2 = (const float*)d_in[10];
    const float* enc_ln_g   = (const float*)d_in[11];
    const float* enc_ln_b   = (const float*)d_in[12];
    const float* dec_sa_w   = (const float*)d_in[13];
    const float* dec_sa_b   = (const float*)d_in[14];
    const float* dec_ca_w   = (const float*)d_in[15];
    const float* dec_ca_b   = (const float*)d_in[16];
    const float* dec_ffn_w1 = (const float*)d_in[17];
    const float* dec_ffn_b1 = (const float*)d_in[18];
    const float* dec_ffn_w2 = (const float*)d_in[19];
    const float* dec_ffn_b2 = (const float*)d_in[20];
    const float* dec_ln_g   = (const float*)d_in[21];
    const float* dec_ln_b   = (const float*)d_in[22];
    const float* out_w      = (const float*)d_in[23];
    const float* out_b      = (const float*)d_in[24];

    cudaFuncSetAttribute(flash_k, cudaFuncAttributeMaxDynamicSharedMemorySize, FA_SMEM);

    float *px, *py, *pxr, *pyr, *pqkv, *pctx, *ppart, *pffn;
    float *wEA, *wEF1, *wEF2, *wDS, *wDC, *wDF1, *wDF2;
    cudaGetSymbolAddress((void**)&px,    g_x);
    cudaGetSymbolAddress((void**)&py,    g_y);
    cudaGetSymbolAddress((void**)&pxr,   g_xr);
    cudaGetSymbolAddress((void**)&pyr,   g_yr);
    cudaGetSymbolAddress((void**)&pqkv,  g_qkv);
    cudaGetSymbolAddress((void**)&pctx,  g_ctx);
    cudaGetSymbolAddress((void**)&ppart, g_part);
    cudaGetSymbolAddress((void**)&pffn,  g_ffn);
    cudaGetSymbolAddress((void**)&wEA,   g_wEA);
    cudaGetSymbolAddress((void**)&wEF1,  g_wEF1);
    cudaGetSymbolAddress((void**)&wEF2,  g_wEF2);
    cudaGetSymbolAddress((void**)&wDS,   g_wDS);
    cudaGetSymbolAddress((void**)&wDC,   g_wDC);
    cudaGetSymbolAddress((void**)&wDF1,  g_wDF1);
    cudaGetSymbolAddress((void**)&wDF2,  g_wDF2);

    // -------- pre-round weights (out_w converted in-kernel by final GEMM) --------
    CVT(enc_attn_w, wEA,  (ll)LEn * 4 * Dm * Dm);
    CVT(enc_ffn_w1, wEF1, (ll)LEn * Dm * DFFn);
    CVT(enc_ffn_w2, wEF2, (ll)LEn * DFFn * Dm);
    CVT(dec_sa_w,   wDS,  (ll)LDn * 4 * Dm * Dm);
    CVT(dec_ca_w,   wDC,  (ll)LDn * 4 * Dm * Dm);
    CVT(dec_ffn_w1, wDF1, (ll)LDn * Dm * DFFn);
    CVT(dec_ffn_w2, wDF2, (ll)LDn * DFFn * Dm);

    float* pq = pqkv;
    float* pk = pqkv + PSTRIDE;
    float* pv = pqkv + 2 * PSTRIDE;

    // -------- encoder --------
    embed_k<<<NTOK, 256>>>(px, pxr, enc_emb, src, pe);
    for (int i = 0; i < LEn; i++) {
        const float* w4 = wEA + (ll)i * 4 * Dm * Dm;
        const float* b4 = enc_attn_b + (ll)i * 4 * Dm;
        QKV(pxr, pxr, w4, b4, pqkv);
        dim3 fg(Sn / 64, Hn, Bn);
        flash_k<<<fg, 128, FA_SMEM>>>(pq, pk, pv, pctx, src, 0);
        NN_512_split(pctx, w4 + 3 * Dm * Dm, ppart, b4 + 3 * Dm, Dm, 2);
        ln_res_k<<<NTOK, 256>>>(px, pxr, ppart, 2, PSTRIDE,
                                enc_ln_g + (i * 2 + 0) * Dm, enc_ln_b + (i * 2 + 0) * Dm);
        NN_big<true, true, false>(pxr, wEF1 + (ll)i * Dm * DFFn, pffn,
                                  enc_ffn_b1 + i * DFFn, NTOK, DFFn, Dm);
        NN_512_split(pffn, wEF2 + (ll)i * DFFn * Dm, ppart, enc_ffn_b2 + i * Dm,
                     DFFn, 4);
        ln_res_k<<<NTOK, 256>>>(px, pxr, ppart, 4, PSTRIDE,
                                enc_ln_g + (i * 2 + 1) * Dm, enc_ln_b + (i * 2 + 1) * Dm);
    }

    // -------- decoder --------
    embed_k<<<NTOK, 256>>>(py, pyr, dec_emb, tgt, pe);
    for (int i = 0; i < LDn; i++) {
        const float* sw4 = wDS + (ll)i * 4 * Dm * Dm;
        const float* sb4 = dec_sa_b + (ll)i * 4 * Dm;
        QKV(pyr, pyr, sw4, sb4, pqkv);
        dim3 fg(Sn / 64, Hn, Bn);
        flash_k<<<fg, 128, FA_SMEM>>>(pq, pk, pv, pctx, tgt, 1);
        fix_k<<<Bn * Hn, 64>>>(pv, pctx, tgt);
        NN_512_split(pctx, sw4 + 3 * Dm * Dm, ppart, sb4 + 3 * Dm, Dm, 2);
        ln_res_k<<<NTOK, 256>>>(py, pyr, ppart, 2, PSTRIDE,
                                dec_ln_g + (i * 3 + 0) * Dm, dec_ln_b + (i * 3 + 0) * Dm);

        const float* cw4 = wDC + (ll)i * 4 * Dm * Dm;
        const float* cb4 = dec_ca_b + (ll)i * 4 * Dm;
        QKV(pyr, pxr, cw4, cb4, pqkv);
        flash_k<<<fg, 128, FA_SMEM>>>(pq, pk, pv, pctx, src, 0);
        NN_512_split(pctx, cw4 + 3 * Dm * Dm, ppart, cb4 + 3 * Dm, Dm, 2);
        ln_res_k<<<NTOK, 256>>>(py, pyr, ppart, 2, PSTRIDE,
                                dec_ln_g + (i * 3 + 1) * Dm, dec_ln_b + (i * 3 + 1) * Dm);

        NN_big<true, true, false>(pyr, wDF1 + (ll)i * Dm * DFFn, pffn,
                                  dec_ffn_b1 + i * DFFn, NTOK, DFFn, Dm);
        NN_512_split(pffn, wDF2 + (ll)i * DFFn * Dm, ppart, dec_ffn_b2 + i * Dm,
                     DFFn, 4);
        ln_res_k<<<NTOK, 256>>>(py, pyr, ppart, 4, PSTRIDE,
                                dec_ln_g + (i * 3 + 2) * Dm, dec_ln_b + (i * 3 + 2) * Dm);
    }

    // -------- final projection (B converted in-kernel) --------
    NN_big<false, false, true>(pyr, out_w, (float*)d_out, out_b, NTOK, Vn, Dm);
}

// round 12
// speedup vs baseline: 1.0306x; 1.0306x over previous
#include <cuda_runtime.h>
#include <math.h>

// Problem constants
#define Dm   512
#define Hn   8
#define DKn  64
#define Sn   512
#define Bn   4
#define NTOK 2048      // B * S
#define DFFn 2048
#define Vn   32000
#define LEn  6
#define LDn  6

typedef long long ll;

// -------------------- scratch (device globals; no allocation) --------------------
__device__ float g_x   [NTOK * Dm];       // fp32 residual stream (encoder)
__device__ float g_y   [NTOK * Dm];       // fp32 residual stream (decoder)
__device__ float g_xr  [NTOK * Dm];       // tf32-rounded copy of g_x
__device__ float g_yr  [NTOK * Dm];       // tf32-rounded copy of g_y
__device__ float g_qkv [3 * NTOK * Dm];   // rounded
__device__ float g_ctx [NTOK * Dm];       // rounded (flash epilogue)
__device__ float g_part[4 * NTOK * Dm];   // split-K partials (raw fp32)
__device__ float g_ffn [NTOK * DFFn];     // rounded (ffn1 epilogue)

// tf32-rounded weight copies
__device__ float g_wEA [LEn * 4 * Dm * Dm];
__device__ float g_wEF1[LEn * Dm * DFFn];
__device__ float g_wEF2[LEn * DFFn * Dm];
__device__ float g_wDS [LDn * 4 * Dm * Dm];
__device__ float g_wDC [LDn * 4 * Dm * Dm];
__device__ float g_wDF1[LDn * Dm * DFFn];
__device__ float g_wDF2[LDn * DFFn * Dm];
__device__ float g_wO  [Dm * Vn];

// -------------------- helpers --------------------
__device__ __forceinline__ float to_tf32(float x) {
    float y;
    asm("cvt.rna.tf32.f32 %0, %1;" : "=f"(y) : "f"(x));
    return y;
}

__device__ __forceinline__ void mma_tf32(float* d, const unsigned* a, const unsigned* b) {
    asm volatile(
        "mma.sync.aligned.m16n8k8.row.col.f32.tf32.tf32.f32 "
        "{%0,%1,%2,%3}, {%4,%5,%6,%7}, {%8,%9}, {%0,%1,%2,%3};\n"
        : "+f"(d[0]), "+f"(d[1]), "+f"(d[2]), "+f"(d[3])
        : "r"(a[0]), "r"(a[1]), "r"(a[2]), "r"(a[3]), "r"(b[0]), "r"(b[1]));
}

__device__ __forceinline__ unsigned su32(const void* p) {
    return (unsigned)__cvta_generic_to_shared(p);
}
#define CP_ASYNC16(s, g) \
    asm volatile("cp.async.cg.shared.global [%0], [%1], 16;\n" :: "r"(s), "l"(g))
#define CP_COMMIT() asm volatile("cp.async.commit_group;\n" ::: "memory")

// -------------------- tf32 pre-round (weights), MLP=4 grid-stride --------------------
__global__ void cvt_k(const float* __restrict__ in, float* __restrict__ out, int n4) {
    int i0 = blockIdx.x * 256 + threadIdx.x;
    const int stride = gridDim.x * 256;
    float4 v[4];
#pragma unroll
    for (int u = 0; u < 4; u++) {
        int i = i0 + u * stride;
        if (i < n4) v[u] = ((const float4*)in)[i];
    }
#pragma unroll
    for (int u = 0; u < 4; u++) {
        int i = i0 + u * stride;
        if (i < n4) {
            float4 w;
            w.x = to_tf32(v[u].x); w.y = to_tf32(v[u].y);
            w.z = to_tf32(v[u].z); w.w = to_tf32(v[u].w);
            ((float4*)out)[i] = w;
        }
    }
}

// ==================== TF32 multistage tensor-core GEMM ====================
// All operands pre-rounded to tf32. No cvt in the inner loop.
template<int BM, int BN, int BK, int WGM, int WGN, int NTH, int STAGES, bool RELU, bool ROUND>
__global__ void __launch_bounds__(NTH)
gemm_tc(const float* __restrict__ A, const float* __restrict__ Aalt,
        const float* __restrict__ B, float* __restrict__ C,
        const float* __restrict__ bias,
        int K, int lda, int ldb, int ldc,
        ll sAz, ll sBz, ll sCz, int biasStride, int biasZ0) {
    const int z = blockIdx.z;
    if (Aalt != nullptr && z > 0) A = Aalt;
    A += (ll)z * sAz;
    B += (ll)z * sBz;
    C += (ll)z * sCz;
    if (bias) {
        if (biasZ0 && z > 0) bias = nullptr;
        else bias += (ll)z * biasStride;
    }

    const int tid = threadIdx.x;
    const int lane = tid & 31, warp = tid >> 5;
    const int wm = warp / WGN, wn = warp % WGN;
    constexpr int WTM = BM / WGM, WTN = BN / WGN;
    constexpr int MT = WTM / 16, NT = WTN / 8;
    const int row0 = blockIdx.y * BM, col0 = blockIdx.x * BN;
    const int g = lane >> 2, tg = lane & 3;

    extern __shared__ float smem[];
    constexpr int AL = BK + 4;
    constexpr int BL = BN + 8;
    constexpr int ASZ = BM * AL;
    constexpr int BSZ = BK * BL;
    float* Asm = smem;
    float* Bsm = smem + STAGES * ASZ;

    constexpr int CA = BM * BK / (4 * NTH);
    constexpr int CB = BK * BN / (4 * NTH);

    auto issue = [&](int it, int st) {
        const int k0 = it * BK;
        float* as = Asm + st * ASZ;
        float* bs = Bsm + st * BSZ;
#pragma unroll
        for (int i = 0; i < CA; i++) {
            int t = tid + i * NTH;
            int r = t / (BK / 4), kq = (t % (BK / 4)) * 4;
            CP_ASYNC16(su32(as + r * AL + kq), A + (ll)(row0 + r) * lda + k0 + kq);
        }
#pragma unroll
        for (int i = 0; i < CB; i++) {
            int t = tid + i * NTH;
            int r = t / (BN / 4), nq = (t % (BN / 4)) * 4;
            CP_ASYNC16(su32(bs + r * BL + nq), B + (ll)(k0 + r) * ldb + col0 + nq);
        }
        CP_COMMIT();
    };

    float acc[MT][NT][4] = {};
    const int nIt = K / BK;

#pragma unroll
    for (int s = 0; s < STAGES - 1; s++)
        if (s < nIt) issue(s, s);

    for (int it = 0; it < nIt; it++) {
        asm volatile("cp.async.wait_group %0;\n" :: "n"(STAGES - 2) : "memory");
        __syncthreads();
        const int pre = it + STAGES - 1;
        if (pre < nIt) issue(pre, pre % STAGES);
        else CP_COMMIT();

        const float* as = Asm + (it % STAGES) * ASZ;
        const float* bs = Bsm + (it % STAGES) * BSZ;

#pragma unroll
        for (int ks = 0; ks < BK / 8; ks++) {
            const int kb = ks * 8;
            unsigned af[MT][4], bf[NT][2];
#pragma unroll
            for (int mt = 0; mt < MT; mt++) {
                int r = wm * WTM + mt * 16 + g;
                af[mt][0] = __float_as_uint(as[r * AL + kb + tg]);
                af[mt][1] = __float_as_uint(as[(r + 8) * AL + kb + tg]);
                af[mt][2] = __float_as_uint(as[r * AL + kb + tg + 4]);
                af[mt][3] = __float_as_uint(as[(r + 8) * AL + kb + tg + 4]);
            }
#pragma unroll
            for (int nt = 0; nt < NT; nt++) {
                int c = wn * WTN + nt * 8 + g;
                bf[nt][0] = __float_as_uint(bs[(kb + tg) * BL + c]);
                bf[nt][1] = __float_as_uint(bs[(kb + tg + 4) * BL + c]);
            }
#pragma unroll
            for (int mt = 0; mt < MT; mt++)
#pragma unroll
                for (int nt = 0; nt < NT; nt++)
                    mma_tf32(acc[mt][nt], af[mt], bf[nt]);
        }
    }

#pragma unroll
    for (int mt = 0; mt < MT; mt++) {
#pragma unroll
        for (int nt = 0; nt < NT; nt++) {
            int r = row0 + wm * WTM + mt * 16 + g;
            int c = col0 + wn * WTN + nt * 8 + tg * 2;
            float b0 = 0.f, b1 = 0.f;
            if (bias) { b0 = bias[c]; b1 = bias[c + 1]; }
            float2 v0, v1;
            v0.x = acc[mt][nt][0] + b0; v0.y = acc[mt][nt][1] + b1;
            v1.x = acc[mt][nt][2] + b0; v1.y = acc[mt][nt][3] + b1;
            if (RELU) {
                v0.x = fmaxf(v0.x, 0.f); v0.y = fmaxf(v0.y, 0.f);
                v1.x = fmaxf(v1.x, 0.f); v1.y = fmaxf(v1.y, 0.f);
            }
            if (ROUND) {
                v0.x = to_tf32(v0.x); v0.y = to_tf32(v0.y);
                v1.x = to_tf32(v1.x); v1.y = to_tf32(v1.y);
            }
            *(float2*)(C + (ll)r * ldc + c) = v0;
            *(float2*)(C + (ll)(r + 8) * ldc + c) = v1;
        }
    }
}

// ==================== fused flash attention (R8 structure + causal tile-skip) ====================
// Q/K/V pre-rounded. K+V double-buffered via cp.async (one group per tile).
// Causal mode processes only k-tiles kt <= qt (skipped tiles contribute exactly 0
// for valid rows); fully-masked rows (tok==0) corrected afterwards by fix_k.
#define FA_STRIDE 68
#define FA_TILE (64 * FA_STRIDE)
__global__ void __launch_bounds__(128)
flash_k(const float* __restrict__ Q, const float* __restrict__ Kv,
        const float* __restrict__ Vv, float* __restrict__ ctx,
        const int* __restrict__ tok, int causal) {
    extern __shared__ float sm[];
    float* Qs = sm;
    float* Ks = sm + FA_TILE;
    float* Vs = sm + 3 * FA_TILE;
    float* Ps = sm + 5 * FA_TILE;
    int* kmv = (int*)(sm + 6 * FA_TILE);

    const int qt = blockIdx.x, h = blockIdx.y, b = blockIdx.z;
    const int tid = threadIdx.x, lane = tid & 31, w = tid >> 5;
    const int g = lane >> 2, tg = lane & 3;
    const int wrow = w * 16;

    const ll base = (ll)(b * Sn) * Dm + h * DKn;
    const int kp = tid >> 1, half = (tid & 1) * 32;
    const int ktiles = causal ? (qt + 1) : 8;

    auto issueKV = [&](int kt, int buf) {
        const float* ksrc = Kv + base + (ll)(kt * 64 + kp) * Dm + half;
        const float* vsrc = Vv + base + (ll)(kt * 64 + kp) * Dm + half;
        unsigned kdst = su32(Ks + buf * FA_TILE + kp * FA_STRIDE + half);
        unsigned vdst = su32(Vs + buf * FA_TILE + kp * FA_STRIDE + half);
#pragma unroll
        for (int j = 0; j < 32; j += 4) {
            CP_ASYNC16(kdst + j * 4, ksrc + j);
            CP_ASYNC16(vdst + j * 4, vsrc + j);
        }
        CP_COMMIT();
    };

    issueKV(0, 0);

    {   // Q already tf32 — straight copy
        const float* src = Q + base + (ll)(qt * 64 + kp) * Dm + half;
        float* dst = Qs + kp * FA_STRIDE + half;
#pragma unroll
        for (int j = 0; j < 32; j += 4)
            *(float4*)(dst + j) = *(const float4*)(src + j);
    }

    const int qrow0 = qt * 64 + wrow + g, qrow1 = qrow0 + 8;
    float m0 = -1e30f, m1 = -1e30f, l0 = 0.f, l1 = 0.f;
    float acc_o[8][4] = {};

    for (int kt = 0; kt < ktiles; kt++) {
        const int buf = kt & 1;
        if (!causal && tid < 64) kmv[tid] = tok[b * Sn + kt * 64 + tid];
        if (kt + 1 < ktiles) {
            issueKV(kt + 1, buf ^ 1);
            asm volatile("cp.async.wait_group 1;\n" ::: "memory");
        } else {
            asm volatile("cp.async.wait_group 0;\n" ::: "memory");
        }
        __syncthreads();

        const float* Kb = Ks + buf * FA_TILE;
        const float* Vb = Vs + buf * FA_TILE;

        float s[8][4] = {};
#pragma unroll
        for (int kc = 0; kc < 8; kc++) {
            const int kb = kc * 8;
            unsigned af[4];
            af[0] = __float_as_uint(Qs[(wrow + g) * FA_STRIDE + kb + tg]);
            af[1] = __float_as_uint(Qs[(wrow + g + 8) * FA_STRIDE + kb + tg]);
            af[2] = __float_as_uint(Qs[(wrow + g) * FA_STRIDE + kb + tg + 4]);
            af[3] = __float_as_uint(Qs[(wrow + g + 8) * FA_STRIDE + kb + tg + 4]);
#pragma unroll
            for (int nt = 0; nt < 8; nt++) {
                unsigned bf[2];
                bf[0] = __float_as_uint(Kb[(nt * 8 + g) * FA_STRIDE + kb + tg]);
                bf[1] = __float_as_uint(Kb[(nt * 8 + g) * FA_STRIDE + kb + tg + 4]);
                mma_tf32(s[nt], af, bf);
            }
        }

        float vmax0 = -1e30f, vmax1 = -1e30f;
#pragma unroll
        for (int nt = 0; nt < 8; nt++) {
#pragma unroll
            for (int jj = 0; jj < 2; jj++) {
                int ncol = nt * 8 + tg * 2 + jj;
                int kcol = kt * 64 + ncol;
                bool mk0, mk1;
                if (causal) { mk0 = (kcol <= qrow0); mk1 = (kcol <= qrow1); }
                else        { bool km = kmv[ncol] != 0; mk0 = km; mk1 = km; }
                float v0 = mk0 ? s[nt][jj] * 0.125f : -1e9f;
                float v1 = mk1 ? s[nt][2 + jj] * 0.125f : -1e9f;
                s[nt][jj] = v0; s[nt][2 + jj] = v1;
                vmax0 = fmaxf(vmax0, v0); vmax1 = fmaxf(vmax1, v1);
            }
        }
        vmax0 = fmaxf(vmax0, __shfl_xor_sync(0xffffffffu, vmax0, 1));
        vmax0 = fmaxf(vmax0, __shfl_xor_sync(0xffffffffu, vmax0, 2));
        vmax1 = fmaxf(vmax1, __shfl_xor_sync(0xffffffffu, vmax1, 1));
        vmax1 = fmaxf(vmax1, __shfl_xor_sync(0xffffffffu, vmax1, 2));

        float mn0 = fmaxf(m0, vmax0), mn1 = fmaxf(m1, vmax1);
        float a0 = __expf(m0 - mn0), a1 = __expf(m1 - mn1);
        m0 = mn0; m1 = mn1;

        float rs0 = 0.f, rs1 = 0.f;
#pragma unroll
        for (int nt = 0; nt < 8; nt++) {
#pragma unroll
            for (int jj = 0; jj < 2; jj++) {
                int ncol = nt * 8 + tg * 2 + jj;
                float p0 = __expf(s[nt][jj] - mn0);
                float p1 = __expf(s[nt][2 + jj] - mn1);
                rs0 += p0; rs1 += p1;
                Ps[(wrow + g) * FA_STRIDE + ncol] = to_tf32(p0);
                Ps[(wrow + g + 8) * FA_STRIDE + ncol] = to_tf32(p1);
            }
        }
        rs0 += __shfl_xor_sync(0xffffffffu, rs0, 1);
        rs0 += __shfl_xor_sync(0xffffffffu, rs0, 2);
        rs1 += __shfl_xor_sync(0xffffffffu, rs1, 1);
        rs1 += __shfl_xor_sync(0xffffffffu, rs1, 2);
        l0 = l0 * a0 + rs0; l1 = l1 * a1 + rs1;
#pragma unroll
        for (int nt = 0; nt < 8; nt++) {
            acc_o[nt][0] *= a0; acc_o[nt][1] *= a0;
            acc_o[nt][2] *= a1; acc_o[nt][3] *= a1;
        }
        __syncwarp();

#pragma unroll
        for (int kc = 0; kc < 8; kc++) {
            const int kb = kc * 8;
            unsigned af[4];
            af[0] = __float_as_uint(Ps[(wrow + g) * FA_STRIDE + kb + tg]);
            af[1] = __float_as_uint(Ps[(wrow + g + 8) * FA_STRIDE + kb + tg]);
            af[2] = __float_as_uint(Ps[(wrow + g) * FA_STRIDE + kb + tg + 4]);
            af[3] = __float_as_uint(Ps[(wrow + g + 8) * FA_STRIDE + kb + tg + 4]);
#pragma unroll
            for (int nt = 0; nt < 8; nt++) {
                unsigned bf[2];
                bf[0] = __float_as_uint(Vb[(kb + tg) * FA_STRIDE + nt * 8 + g]);
                bf[1] = __float_as_uint(Vb[(kb + tg + 4) * FA_STRIDE + nt * 8 + g]);
                mma_tf32(acc_o[nt], af, bf);
            }
        }
        __syncthreads();
    }

    float inv0 = 1.f / l0, inv1 = 1.f / l1;
#pragma unroll
    for (int nt = 0; nt < 8; nt++) {
        int c = nt * 8 + tg * 2;
        float2 o0, o1;
        o0.x = to_tf32(acc_o[nt][0] * inv0); o0.y = to_tf32(acc_o[nt][1] * inv0);
        o1.x = to_tf32(acc_o[nt][2] * inv1); o1.y = to_tf32(acc_o[nt][3] * inv1);
        *(float2*)(ctx + base + (ll)qrow0 * Dm + c) = o0;
        *(float2*)(ctx + base + (ll)qrow1 * Dm + c) = o1;
    }
}

// -------------------- causal fully-masked-row fixup --------------------
// Rows with tok==0: reference softmax is uniform over ALL Sn keys -> ctx = mean(V).
__global__ void fix_k(const float* __restrict__ Vv, float* __restrict__ ctx,
                      const int* __restrict__ tok) {
    int h = blockIdx.x & (Hn - 1), b = blockIdx.x / Hn;
    int d = threadIdx.x;   // 64
    __shared__ int hasz;
    if (d == 0) hasz = 0;
    __syncthreads();
    for (int q = d; q < Sn; q += 64)
        if (tok[b * Sn + q] == 0) atomicOr(&hasz, 1);
    __syncthreads();
    if (!hasz) return;

    const ll base = (ll)(b * Sn) * Dm + h * DKn;
    float s = 0.f;
    for (int k = 0; k < Sn; k++) s += Vv[base + (ll)k * Dm + d];
    s = to_tf32(s * (1.0f / Sn));
    for (int q = 0; q < Sn; q++)
        if (tok[b * Sn + q] == 0) ctx[base + (ll)q * Dm + d] = s;
}

// -------------------- embedding + PE (dual write: fp32 + tf32) --------------------
__global__ void embed_k(float* __restrict__ out, float* __restrict__ outr,
                        const float* __restrict__ emb,
                        const int* __restrict__ tok, const float* __restrict__ pe) {
    int t = blockIdx.x;
    int s = t & (Sn - 1);
    int tk = tok[t];
    const float scale = 22.627416997969522f;
    int base = t * Dm;
    for (int d = threadIdx.x; d < Dm; d += blockDim.x) {
        float v = emb[tk * Dm + d] * scale + pe[s * Dm + d];
        out[base + d] = v;
        outr[base + d] = to_tf32(v);
    }
}

// -------------------- residual + split-K reduce + LayerNorm (dual write) --------------------
__global__ void ln_res_k(float* __restrict__ x, float* __restrict__ xr,
                         const float* __restrict__ parts, int npart, ll pstride,
                         const float* __restrict__ g, const float* __restrict__ be) {
    int r = blockIdx.x;
    int base = r * Dm;
    int tid = threadIdx.x;
    float v0 = x[base + tid];
    float v1 = x[base + tid + 256];
    for (int p = 0; p < npart; p++) {
        v0 += parts[p * pstride + base + tid];
        v1 += parts[p * pstride + base + tid + 256];
    }

    float s = v0 + v1;
    float sq = v0 * v0 + v1 * v1;
    __shared__ float rs[8], rq[8];
#pragma unroll
    for (int o = 16; o; o >>= 1) {
        s  += __shfl_xor_sync(0xffffffffu, s, o);
        sq += __shfl_xor_sync(0xffffffffu, sq, o);
    }
    if ((tid & 31) == 0) { rs[tid >> 5] = s; rq[tid >> 5] = sq; }
    __syncthreads();
    if (tid < 8) {
        float a1 = rs[tid], a2 = rq[tid];
#pragma unroll
        for (int o = 4; o; o >>= 1) {
            a1 += __shfl_xor_sync(0xffu, a1, o);
            a2 += __shfl_xor_sync(0xffu, a2, o);
        }
        if (tid == 0) { rs[0] = a1; rq[0] = a2; }
    }
    __syncthreads();
    float mu = rs[0] * (1.0f / Dm);
    float var = rq[0] * (1.0f / Dm) - mu * mu;
    float inv = rsqrtf(var + 1e-5f);
    float o0 = g[tid]       * (v0 - mu) * inv + be[tid];
    float o1 = g[tid + 256] * (v1 - mu) * inv + be[tid + 256];
    x[base + tid]        = o0;
    x[base + tid + 256]  = o1;
    xr[base + tid]       = to_tf32(o0);
    xr[base + tid + 256] = to_tf32(o1);
}

// ==================== host orchestration ====================
#define STG 3
static inline int smemBytes(int BM, int BN, int BK) {
    return STG * (BM * (BK + 4) + BK * (BN + 8)) * 4;
}

static void CVT(const float* in, float* out, ll n) {
    int n4 = (int)(n / 4);
    int thr = (n4 + 3) / 4;
    cvt_k<<<(thr + 255) / 256, 256>>>(in, out, n4);
}

template<bool RELU, bool ROUND>
static void NN_big(const float* A, const float* B, float* C, const float* bias,
                   int M, int N, int K) {
    dim3 grid(N / 128, M / 128, 1);
    int sb = smemBytes(128, 128, 32);
    cudaFuncSetAttribute((const void*)gemm_tc<128, 128, 32, 2, 4, 256, STG, RELU, ROUND>,
                         cudaFuncAttributeMaxDynamicSharedMemorySize, sb);
    gemm_tc<128, 128, 32, 2, 4, 256, STG, RELU, ROUND><<<grid, 256, sb>>>(
        A, nullptr, B, C, bias, K, K, N, N, 0, 0, 0, 0, 0);
}

static void NN_512_split(const float* A, const float* B, float* Cpart,
                         const float* bias, int K, int nsplit) {
    int Ksl = K / nsplit;
    dim3 grid(Dm / 64, NTOK / 64, nsplit);
    int sb = smemBytes(64, 64, 32);
    cudaFuncSetAttribute((const void*)gemm_tc<64, 64, 32, 2, 2, 128, STG, false, false>,
                         cudaFuncAttributeMaxDynamicSharedMemorySize, sb);
    gemm_tc<64, 64, 32, 2, 2, 128, STG, false, false><<<grid, 128, sb>>>(
        A, nullptr, B, Cpart, bias, Ksl, K, Dm, Dm,
        (ll)Ksl, (ll)Ksl * Dm, (ll)NTOK * Dm, 0, 1);
}

static void QKV(const float* xq, const float* xkv, const float* w4, const float* b4,
                float* qkv) {
    dim3 grid(Dm / 64, NTOK / 64, 3);
    int sb = smemBytes(64, 64, 32);
    cudaFuncSetAttribute((const void*)gemm_tc<64, 64, 32, 2, 2, 128, STG, false, true>,
                         cudaFuncAttributeMaxDynamicSharedMemorySize, sb);
    gemm_tc<64, 64, 32, 2, 2, 128, STG, false, true><<<grid, 128, sb>>>(
        xq, xkv, w4, qkv, b4, Dm, Dm, Dm, Dm,
        0, (ll)Dm * Dm, (ll)NTOK * Dm, Dm, 0);
}

static const int FA_SMEM = (6 * FA_TILE + 64) * 4;
static const ll PSTRIDE = (ll)NTOK * Dm;

extern "C" void kernel_launch(void* const* d_in, const int* in_sizes, int n_in,
                              void* d_out, int out_size) {
    const int*   src        = (const int*)  d_in[0];
    const int*   tgt        = (const int*)  d_in[1];
    const float* enc_emb    = (const float*)d_in[2];
    const float* dec_emb    = (const float*)d_in[3];
    const float* pe         = (const float*)d_in[4];
    const float* enc_attn_w = (const float*)d_in[5];
    const float* enc_attn_b = (const float*)d_in[6];
    const float* enc_ffn_w1 = (const float*)d_in[7];
    const float* enc_ffn_b1 = (const float*)d_in[8];
    const float* enc_ffn_w2 = (const float*)d_in[9];
    const float* enc_ffn_b2 = (const float*)d_in[10];
    const float* enc_ln_g   = (const float*)d_in[11];
    const float* enc_ln_b   = (const float*)d_in[12];
    const float* dec_sa_w   = (const float*)d_in[13];
    const float* dec_sa_b   = (const float*)d_in[14];
    const float* dec_ca_w   = (const float*)d_in[15];
    const float* dec_ca_b   = (const float*)d_in[16];
    const float* dec_ffn_w1 = (const float*)d_in[17];
    const float* dec_ffn_b1 = (const float*)d_in[18];
    const float* dec_ffn_w2 = (const float*)d_in[19];
    const float* dec_ffn_b2 = (const float*)d_in[20];
    const float* dec_ln_g   = (const float*)d_in[21];
    const float* dec_ln_b   = (const float*)d_in[22];
    const float* out_w      = (const float*)d_in[23];
    const float* out_b      = (const float*)d_in[24];

    cudaFuncSetAttribute(flash_k, cudaFuncAttributeMaxDynamicSharedMemorySize, FA_SMEM);

    float *px, *py, *pxr, *pyr, *pqkv, *pctx, *ppart, *pffn;
    float *wEA, *wEF1, *wEF2, *wDS, *wDC, *wDF1, *wDF2, *wO;
    cudaGetSymbolAddress((void**)&px,    g_x);
    cudaGetSymbolAddress((void**)&py,    g_y);
    cudaGetSymbolAddress((void**)&pxr,   g_xr);
    cudaGetSymbolAddress((void**)&pyr,   g_yr);
    cudaGetSymbolAddress((void**)&pqkv,  g_qkv);
    cudaGetSymbolAddress((void**)&pctx,  g_ctx);
    cudaGetSymbolAddress((void**)&ppart, g_part);
    cudaGetSymbolAddress((void**)&pffn,  g_ffn);
    cudaGetSymbolAddress((void**)&wEA,   g_wEA);
    cudaGetSymbolAddress((void**)&wEF1,  g_wEF1);
    cudaGetSymbolAddress((void**)&wEF2,  g_wEF2);
    cudaGetSymbolAddress((void**)&wDS,   g_wDS);
    cudaGetSymbolAddress((void**)&wDC,   g_wDC);
    cudaGetSymbolAddress((void**)&wDF1,  g_wDF1);
    cudaGetSymbolAddress((void**)&wDF2,  g_wDF2);
    cudaGetSymbolAddress((void**)&wO,    g_wO);

    // -------- pre-round all weights to tf32 --------
    CVT(enc_attn_w, wEA,  (ll)LEn * 4 * Dm * Dm);
    CVT(enc_ffn_w1, wEF1, (ll)LEn * Dm * DFFn);
    CVT(enc_ffn_w2, wEF2, (ll)LEn * DFFn * Dm);
    CVT(dec_sa_w,   wDS,  (ll)LDn * 4 * Dm * Dm);
    CVT(dec_ca_w,   wDC,  (ll)LDn * 4 * Dm * Dm);
    CVT(dec_ffn_w1, wDF1, (ll)LDn * Dm * DFFn);
    CVT(dec_ffn_w2, wDF2, (ll)LDn * DFFn * Dm);
    CVT(out_w,      wO,   (ll)Dm * Vn);

    float* pq = pqkv;
    float* pk = pqkv + PSTRIDE;
    float* pv = pqkv + 2 * PSTRIDE;

    // -------- encoder --------
    embed_k<<<NTOK, 256>>>(px, pxr, enc_emb, src, pe);
    for (int i = 0; i < LEn; i++) {
        const float* w4 = wEA + (ll)i * 4 * Dm * Dm;
        const float* b4 = enc_attn_b + (ll)i * 4 * Dm;
        QKV(pxr, pxr, w4, b4, pqkv);
        dim3 fg(Sn / 64, Hn, Bn);
        flash_k<<<fg, 128, FA_SMEM>>>(pq, pk, pv, pctx, src, 0);
        NN_512_split(pctx, w4 + 3 * Dm * Dm, ppart, b4 + 3 * Dm, Dm, 2);
        ln_res_k<<<NTOK, 256>>>(px, pxr, ppart, 2, PSTRIDE,
                                enc_ln_g + (i * 2 + 0) * Dm, enc_ln_b + (i * 2 + 0) * Dm);
        NN_big<true, true>(pxr, wEF1 + (ll)i * Dm * DFFn, pffn,
                           enc_ffn_b1 + i * DFFn, NTOK, DFFn, Dm);
        NN_512_split(pffn, wEF2 + (ll)i * DFFn * Dm, ppart, enc_ffn_b2 + i * Dm,
                     DFFn, 4);
        ln_res_k<<<NTOK, 256>>>(px, pxr, ppart, 4, PSTRIDE,
                                enc_ln_g + (i * 2 + 1) * Dm, enc_ln_b + (i * 2 + 1) * Dm);
    }

    // -------- decoder --------
    embed_k<<<NTOK, 256>>>(py, pyr, dec_emb, tgt, pe);
    for (int i = 0; i < LDn; i++) {
        const float* sw4 = wDS + (ll)i * 4 * Dm * Dm;
        const float* sb4 = dec_sa_b + (ll)i * 4 * Dm;
        QKV(pyr, pyr, sw4, sb4, pqkv);
        dim3 fg(Sn / 64, Hn, Bn);
        flash_k<<<fg, 128, FA_SMEM>>>(pq, pk, pv, pctx, tgt, 1);
        fix_k<<<Bn * Hn, 64>>>(pv, pctx, tgt);
        NN_512_split(pctx, sw4 + 3 * Dm * Dm, ppart, sb4 + 3 * Dm, Dm, 2);
        ln_res_k<<<NTOK, 256>>>(py, pyr, ppart, 2, PSTRIDE,
                                dec_ln_g + (i * 3 + 0) * Dm, dec_ln_b + (i * 3 + 0) * Dm);

        const float* cw4 = wDC + (ll)i * 4 * Dm * Dm;
        const float* cb4 = dec_ca_b + (ll)i * 4 * Dm;
        QKV(pyr, pxr, cw4, cb4, pqkv);
        flash_k<<<fg, 128, FA_SMEM>>>(pq, pk, pv, pctx, src, 0);
        NN_512_split(pctx, cw4 + 3 * Dm * Dm, ppart, cb4 + 3 * Dm, Dm, 2);
        ln_res_k<<<NTOK, 256>>>(py, pyr, ppart, 2, PSTRIDE,
                                dec_ln_g + (i * 3 + 1) * Dm, dec_ln_b + (i * 3 + 1) * Dm);

        NN_big<true, true>(pyr, wDF1 + (ll)i * Dm * DFFn, pffn,
                           dec_ffn_b1 + i * DFFn, NTOK, DFFn, Dm);
        NN_512_split(pffn, wDF2 + (ll)i * DFFn * Dm, ppart, dec_ffn_b2 + i * Dm,
                     DFFn, 4);
        ln_res_k<<<NTOK, 256>>>(py, pyr, ppart, 4, PSTRIDE,
                                dec_ln_g + (i * 3 + 2) * Dm, dec_ln_b + (i * 3 + 2) * Dm);
    }

    // -------- final projection --------
    NN_big<false, false>(pyr, wO, (float*)d_out, out_b, NTOK, Vn, Dm);
}

// round 13
// speedup vs baseline: 1.0348x; 1.0041x over previous
#include <cuda_runtime.h>
#include <math.h>

// Problem constants
#define Dm   512
#define Hn   8
#define DKn  64
#define Sn   512
#define Bn   4
#define NTOK 2048      // B * S
#define DFFn 2048
#define Vn   32000
#define LEn  6
#define LDn  6

typedef long long ll;

// -------------------- scratch (device globals; no allocation) --------------------
__device__ float g_x   [NTOK * Dm];
__device__ float g_y   [NTOK * Dm];
__device__ float g_xr  [NTOK * Dm];
__device__ float g_yr  [NTOK * Dm];
__device__ float g_qkv [3 * NTOK * Dm];
__device__ float g_ctx [NTOK * Dm];
__device__ float g_part[4 * NTOK * Dm];
__device__ float g_ffn [NTOK * DFFn];

// tf32-rounded weight copies
__device__ float g_wEA [LEn * 4 * Dm * Dm];
__device__ float g_wEF1[LEn * Dm * DFFn];
__device__ float g_wEF2[LEn * DFFn * Dm];
__device__ float g_wDS [LDn * 4 * Dm * Dm];
__device__ float g_wDC [LDn * 4 * Dm * Dm];
__device__ float g_wDF1[LDn * Dm * DFFn];
__device__ float g_wDF2[LDn * DFFn * Dm];
__device__ float g_wO  [Dm * Vn];

// -------------------- helpers --------------------
__device__ __forceinline__ float to_tf32(float x) {
    float y;
    asm("cvt.rna.tf32.f32 %0, %1;" : "=f"(y) : "f"(x));
    return y;
}

__device__ __forceinline__ void mma_tf32(float* d, const unsigned* a, const unsigned* b) {
    asm volatile(
        "mma.sync.aligned.m16n8k8.row.col.f32.tf32.tf32.f32 "
        "{%0,%1,%2,%3}, {%4,%5,%6,%7}, {%8,%9}, {%0,%1,%2,%3};\n"
        : "+f"(d[0]), "+f"(d[1]), "+f"(d[2]), "+f"(d[3])
        : "r"(a[0]), "r"(a[1]), "r"(a[2]), "r"(a[3]), "r"(b[0]), "r"(b[1]));
}

__device__ __forceinline__ unsigned su32(const void* p) {
    return (unsigned)__cvta_generic_to_shared(p);
}
#define CP_ASYNC16(s, g) \
    asm volatile("cp.async.cg.shared.global [%0], [%1], 16;\n" :: "r"(s), "l"(g))
#define CP_COMMIT() asm volatile("cp.async.commit_group;\n" ::: "memory")

// -------------------- tf32 pre-round (weights) --------------------
__global__ void cvt_k(const float* __restrict__ in, float* __restrict__ out, int n4) {
    int i0 = blockIdx.x * 256 + threadIdx.x;
    const int stride = gridDim.x * 256;
    float4 v[4];
#pragma unroll
    for (int u = 0; u < 4; u++) {
        int i = i0 + u * stride;
        if (i < n4) v[u] = ((const float4*)in)[i];
    }
#pragma unroll
    for (int u = 0; u < 4; u++) {
        int i = i0 + u * stride;
        if (i < n4) {
            float4 w;
            w.x = to_tf32(v[u].x); w.y = to_tf32(v[u].y);
            w.z = to_tf32(v[u].z); w.w = to_tf32(v[u].w);
            ((float4*)out)[i] = w;
        }
    }
}

// ==================== TF32 multistage tensor-core GEMM ====================
template<int BM, int BN, int BK, int WGM, int WGN, int NTH, int STAGES, bool RELU, bool ROUND>
__global__ void __launch_bounds__(NTH)
gemm_tc(const float* __restrict__ A, const float* __restrict__ Aalt,
        const float* __restrict__ B, float* __restrict__ C,
        const float* __restrict__ bias,
        int K, int lda, int ldb, int ldc,
        ll sAz, ll sBz, ll sCz, int biasStride, int biasZ0) {
    const int z = blockIdx.z;
    if (Aalt != nullptr && z > 0) A = Aalt;
    A += (ll)z * sAz;
    B += (ll)z * sBz;
    C += (ll)z * sCz;
    if (bias) {
        if (biasZ0 && z > 0) bias = nullptr;
        else bias += (ll)z * biasStride;
    }

    const int tid = threadIdx.x;
    const int lane = tid & 31, warp = tid >> 5;
    const int wm = warp / WGN, wn = warp % WGN;
    constexpr int WTM = BM / WGM, WTN = BN / WGN;
    constexpr int MT = WTM / 16, NT = WTN / 8;
    const int row0 = blockIdx.y * BM, col0 = blockIdx.x * BN;
    const int g = lane >> 2, tg = lane & 3;

    extern __shared__ float smem[];
    constexpr int AL = BK + 4;
    constexpr int BL = BN + 8;
    constexpr int ASZ = BM * AL;
    constexpr int BSZ = BK * BL;
    float* Asm = smem;
    float* Bsm = smem + STAGES * ASZ;

    constexpr int CA = BM * BK / (4 * NTH);
    constexpr int CB = BK * BN / (4 * NTH);

    auto issue = [&](int it, int st) {
        const int k0 = it * BK;
        float* as = Asm + st * ASZ;
        float* bs = Bsm + st * BSZ;
#pragma unroll
        for (int i = 0; i < CA; i++) {
            int t = tid + i * NTH;
            int r = t / (BK / 4), kq = (t % (BK / 4)) * 4;
            CP_ASYNC16(su32(as + r * AL + kq), A + (ll)(row0 + r) * lda + k0 + kq);
        }
#pragma unroll
        for (int i = 0; i < CB; i++) {
            int t = tid + i * NTH;
            int r = t / (BN / 4), nq = (t % (BN / 4)) * 4;
            CP_ASYNC16(su32(bs + r * BL + nq), B + (ll)(k0 + r) * ldb + col0 + nq);
        }
        CP_COMMIT();
    };

    float acc[MT][NT][4] = {};
    const int nIt = K / BK;

#pragma unroll
    for (int s = 0; s < STAGES - 1; s++)
        if (s < nIt) issue(s, s);

    for (int it = 0; it < nIt; it++) {
        asm volatile("cp.async.wait_group %0;\n" :: "n"(STAGES - 2) : "memory");
        __syncthreads();
        const int pre = it + STAGES - 1;
        if (pre < nIt) issue(pre, pre % STAGES);
        else CP_COMMIT();

        const float* as = Asm + (it % STAGES) * ASZ;
        const float* bs = Bsm + (it % STAGES) * BSZ;

#pragma unroll
        for (int ks = 0; ks < BK / 8; ks++) {
            const int kb = ks * 8;
            unsigned af[MT][4], bf[NT][2];
#pragma unroll
            for (int mt = 0; mt < MT; mt++) {
                int r = wm * WTM + mt * 16 + g;
                af[mt][0] = __float_as_uint(as[r * AL + kb + tg]);
                af[mt][1] = __float_as_uint(as[(r + 8) * AL + kb + tg]);
                af[mt][2] = __float_as_uint(as[r * AL + kb + tg + 4]);
                af[mt][3] = __float_as_uint(as[(r + 8) * AL + kb + tg + 4]);
            }
#pragma unroll
            for (int nt = 0; nt < NT; nt++) {
                int c = wn * WTN + nt * 8 + g;
                bf[nt][0] = __float_as_uint(bs[(kb + tg) * BL + c]);
                bf[nt][1] = __float_as_uint(bs[(kb + tg + 4) * BL + c]);
            }
#pragma unroll
            for (int mt = 0; mt < MT; mt++)
#pragma unroll
                for (int nt = 0; nt < NT; nt++)
                    mma_tf32(acc[mt][nt], af[mt], bf[nt]);
        }
    }

#pragma unroll
    for (int mt = 0; mt < MT; mt++) {
#pragma unroll
        for (int nt = 0; nt < NT; nt++) {
            int r = row0 + wm * WTM + mt * 16 + g;
            int c = col0 + wn * WTN + nt * 8 + tg * 2;
            float b0 = 0.f, b1 = 0.f;
            if (bias) { b0 = bias[c]; b1 = bias[c + 1]; }
            float2 v0, v1;
            v0.x = acc[mt][nt][0] + b0; v0.y = acc[mt][nt][1] + b1;
            v1.x = acc[mt][nt][2] + b0; v1.y = acc[mt][nt][3] + b1;
            if (RELU) {
                v0.x = fmaxf(v0.x, 0.f); v0.y = fmaxf(v0.y, 0.f);
                v1.x = fmaxf(v1.x, 0.f); v1.y = fmaxf(v1.y, 0.f);
            }
            if (ROUND) {
                v0.x = to_tf32(v0.x); v0.y = to_tf32(v0.y);
                v1.x = to_tf32(v1.x); v1.y = to_tf32(v1.y);
            }
            *(float2*)(C + (ll)r * ldc + c) = v0;
            *(float2*)(C + (ll)(r + 8) * ldc + c) = v1;
        }
    }
}

// ==================== fused flash attention ====================
// K+V double-buffered via cp.async. Causal: only k-tiles kt <= qt (skipped
// tiles contribute exactly 0 for valid rows); rows with tok==0 are NOT stored
// by regular blocks — the extra qt==8 blocks write mean(V) for those rows
// (reference semantics: fully-masked row -> uniform softmax over all keys).
#define FA_STRIDE 68
#define FA_TILE (64 * FA_STRIDE)
__global__ void __launch_bounds__(128)
flash_k(const float* __restrict__ Q, const float* __restrict__ Kv,
        const float* __restrict__ Vv, float* __restrict__ ctx,
        const int* __restrict__ tok, int causal) {
    extern __shared__ float sm[];
    float* Qs = sm;
    float* Ks = sm + FA_TILE;
    float* Vs = sm + 3 * FA_TILE;
    float* Ps = sm + 5 * FA_TILE;
    int* kmv = (int*)(sm + 6 * FA_TILE);

    const int qt = blockIdx.x, h = blockIdx.y, b = blockIdx.z;
    const int tid = threadIdx.x, lane = tid & 31, w = tid >> 5;
    const ll base = (ll)(b * Sn) * Dm + h * DKn;

    // ---- fixup blocks (causal grid has qt==8): ctx[tok==0 rows] = mean(V) ----
    if (qt == 8) {
        __shared__ int hasz;
        __shared__ float part2[2][64];
        if (tid == 0) hasz = 0;
        __syncthreads();
        for (int q = tid; q < Sn; q += 128)
            if (tok[b * Sn + q] == 0) hasz = 1;
        __syncthreads();
        if (!hasz) return;
        int d = tid & 63, hf = tid >> 6;
        float s = 0.f;
        for (int k = hf * 256; k < hf * 256 + 256; k++)
            s += Vv[base + (ll)k * Dm + d];
        part2[hf][d] = s;
        __syncthreads();
        if (tid < 64) {
            float m = to_tf32((part2[0][d] + part2[1][d]) * (1.0f / Sn));
            for (int q = 0; q < Sn; q++)
                if (tok[b * Sn + q] == 0) ctx[base + (ll)q * Dm + d] = m;
        }
        return;
    }

    const int g = lane >> 2, tg = lane & 3;
    const int wrow = w * 16;
    const int kp = tid >> 1, half = (tid & 1) * 32;
    const int ktiles = causal ? (qt + 1) : 8;

    auto issueKV = [&](int kt, int buf) {
        const float* ksrc = Kv + base + (ll)(kt * 64 + kp) * Dm + half;
        const float* vsrc = Vv + base + (ll)(kt * 64 + kp) * Dm + half;
        unsigned kdst = su32(Ks + buf * FA_TILE + kp * FA_STRIDE + half);
        unsigned vdst = su32(Vs + buf * FA_TILE + kp * FA_STRIDE + half);
#pragma unroll
        for (int j = 0; j < 32; j += 4) {
            CP_ASYNC16(kdst + j * 4, ksrc + j);
            CP_ASYNC16(vdst + j * 4, vsrc + j);
        }
        CP_COMMIT();
    };

    issueKV(0, 0);

    {   // Q already tf32 — straight copy
        const float* src = Q + base + (ll)(qt * 64 + kp) * Dm + half;
        float* dst = Qs + kp * FA_STRIDE + half;
#pragma unroll
        for (int j = 0; j < 32; j += 4)
            *(float4*)(dst + j) = *(const float4*)(src + j);
    }

    const int qrow0 = qt * 64 + wrow + g, qrow1 = qrow0 + 8;
    bool qv0 = true, qv1 = true;
    if (causal) { qv0 = tok[b * Sn + qrow0] != 0; qv1 = tok[b * Sn + qrow1] != 0; }

    float m0 = -1e30f, m1 = -1e30f, l0 = 0.f, l1 = 0.f;
    float acc_o[8][4] = {};

    for (int kt = 0; kt < ktiles; kt++) {
        const int buf = kt & 1;
        if (!causal && tid < 64) kmv[tid] = tok[b * Sn + kt * 64 + tid];
        if (kt + 1 < ktiles) {
            issueKV(kt + 1, buf ^ 1);
            asm volatile("cp.async.wait_group 1;\n" ::: "memory");
        } else {
            asm volatile("cp.async.wait_group 0;\n" ::: "memory");
        }
        __syncthreads();

        const float* Kb = Ks + buf * FA_TILE;
        const float* Vb = Vs + buf * FA_TILE;

        float s[8][4] = {};
#pragma unroll
        for (int kc = 0; kc < 8; kc++) {
            const int kb = kc * 8;
            unsigned af[4];
            af[0] = __float_as_uint(Qs[(wrow + g) * FA_STRIDE + kb + tg]);
            af[1] = __float_as_uint(Qs[(wrow + g + 8) * FA_STRIDE + kb + tg]);
            af[2] = __float_as_uint(Qs[(wrow + g) * FA_STRIDE + kb + tg + 4]);
            af[3] = __float_as_uint(Qs[(wrow + g + 8) * FA_STRIDE + kb + tg + 4]);
#pragma unroll
            for (int nt = 0; nt < 8; nt++) {
                unsigned bf[2];
                bf[0] = __float_as_uint(Kb[(nt * 8 + g) * FA_STRIDE + kb + tg]);
                bf[1] = __float_as_uint(Kb[(nt * 8 + g) * FA_STRIDE + kb + tg + 4]);
                mma_tf32(s[nt], af, bf);
            }
        }

        float vmax0 = -1e30f, vmax1 = -1e30f;
#pragma unroll
        for (int nt = 0; nt < 8; nt++) {
#pragma unroll
            for (int jj = 0; jj < 2; jj++) {
                int ncol = nt * 8 + tg * 2 + jj;
                int kcol = kt * 64 + ncol;
                bool mk0, mk1;
                if (causal) { mk0 = (kcol <= qrow0); mk1 = (kcol <= qrow1); }
                else        { bool km = kmv[ncol] != 0; mk0 = km; mk1 = km; }
                float v0 = mk0 ? s[nt][jj] * 0.125f : -1e9f;
                float v1 = mk1 ? s[nt][2 + jj] * 0.125f : -1e9f;
                s[nt][jj] = v0; s[nt][2 + jj] = v1;
                vmax0 = fmaxf(vmax0, v0); vmax1 = fmaxf(vmax1, v1);
            }
        }
        vmax0 = fmaxf(vmax0, __shfl_xor_sync(0xffffffffu, vmax0, 1));
        vmax0 = fmaxf(vmax0, __shfl_xor_sync(0xffffffffu, vmax0, 2));
        vmax1 = fmaxf(vmax1, __shfl_xor_sync(0xffffffffu, vmax1, 1));
        vmax1 = fmaxf(vmax1, __shfl_xor_sync(0xffffffffu, vmax1, 2));

        float mn0 = fmaxf(m0, vmax0), mn1 = fmaxf(m1, vmax1);
        float a0 = __expf(m0 - mn0), a1 = __expf(m1 - mn1);
        m0 = mn0; m1 = mn1;

        float rs0 = 0.f, rs1 = 0.f;
#pragma unroll
        for (int nt = 0; nt < 8; nt++) {
#pragma unroll
            for (int jj = 0; jj < 2; jj++) {
                int ncol = nt * 8 + tg * 2 + jj;
                float p0 = __expf(s[nt][jj] - mn0);
                float p1 = __expf(s[nt][2 + jj] - mn1);
                rs0 += p0; rs1 += p1;
                Ps[(wrow + g) * FA_STRIDE + ncol] = to_tf32(p0);
                Ps[(wrow + g + 8) * FA_STRIDE + ncol] = to_tf32(p1);
            }
        }
        rs0 += __shfl_xor_sync(0xffffffffu, rs0, 1);
        rs0 += __shfl_xor_sync(0xffffffffu, rs0, 2);
        rs1 += __shfl_xor_sync(0xffffffffu, rs1, 1);
        rs1 += __shfl_xor_sync(0xffffffffu, rs1, 2);
        l0 = l0 * a0 + rs0; l1 = l1 * a1 + rs1;
#pragma unroll
        for (int nt = 0; nt < 8; nt++) {
            acc_o[nt][0] *= a0; acc_o[nt][1] *= a0;
            acc_o[nt][2] *= a1; acc_o[nt][3] *= a1;
        }
        __syncwarp();

#pragma unroll
        for (int kc = 0; kc < 8; kc++) {
            const int kb = kc * 8;
            unsigned af[4];
            af[0] = __float_as_uint(Ps[(wrow + g) * FA_STRIDE + kb + tg]);
            af[1] = __float_as_uint(Ps[(wrow + g + 8) * FA_STRIDE + kb + tg]);
            af[2] = __float_as_uint(Ps[(wrow + g) * FA_STRIDE + kb + tg + 4]);
            af[3] = __float_as_uint(Ps[(wrow + g + 8) * FA_STRIDE + kb + tg + 4]);
#pragma unroll
            for (int nt = 0; nt < 8; nt++) {
                unsigned bf[2];
                bf[0] = __float_as_uint(Vb[(kb + tg) * FA_STRIDE + nt * 8 + g]);
                bf[1] = __float_as_uint(Vb[(kb + tg + 4) * FA_STRIDE + nt * 8 + g]);
                mma_tf32(acc_o[nt], af, bf);
            }
        }
        __syncthreads();
    }

    float inv0 = 1.f / l0, inv1 = 1.f / l1;
#pragma unroll
    for (int nt = 0; nt < 8; nt++) {
        int c = nt * 8 + tg * 2;
        if (qv0) {
            float2 o0;
            o0.x = to_tf32(acc_o[nt][0] * inv0); o0.y = to_tf32(acc_o[nt][1] * inv0);
            *(float2*)(ctx + base + (ll)qrow0 * Dm + c) = o0;
        }
        if (qv1) {
            float2 o1;
            o1.x = to_tf32(acc_o[nt][2] * inv1); o1.y = to_tf32(acc_o[nt][3] * inv1);
            *(float2*)(ctx + base + (ll)qrow1 * Dm + c) = o1;
        }
    }
}

// -------------------- embedding + PE (dual write: fp32 + tf32) --------------------
__global__ void embed_k(float* __restrict__ out, float* __restrict__ outr,
                        const float* __restrict__ emb,
                        const int* __restrict__ tok, const float* __restrict__ pe) {
    int t = blockIdx.x;
    int s = t & (Sn - 1);
    int tk = tok[t];
    const float scale = 22.627416997969522f;
    int base = t * Dm;
    for (int d = threadIdx.x; d < Dm; d += blockDim.x) {
        float v = emb[tk * Dm + d] * scale + pe[s * Dm + d];
        out[base + d] = v;
        outr[base + d] = to_tf32(v);
    }
}

// -------------------- residual + split-K reduce + LayerNorm (dual write) --------------------
__global__ void ln_res_k(float* __restrict__ x, float* __restrict__ xr,
                         const float* __restrict__ parts, int npart, ll pstride,
                         const float* __restrict__ g, const float* __restrict__ be) {
    int r = blockIdx.x;
    int base = r * Dm;
    int tid = threadIdx.x;
    float v0 = x[base + tid];
    float v1 = x[base + tid + 256];
    for (int p = 0; p < npart; p++) {
        v0 += parts[p * pstride + base + tid];
        v1 += parts[p * pstride + base + tid + 256];
    }

    float s = v0 + v1;
    float sq = v0 * v0 + v1 * v1;
    __shared__ float rs[8], rq[8];
#pragma unroll
    for (int o = 16; o; o >>= 1) {
        s  += __shfl_xor_sync(0xffffffffu, s, o);
        sq += __shfl_xor_sync(0xffffffffu, sq, o);
    }
    if ((tid & 31) == 0) { rs[tid >> 5] = s; rq[tid >> 5] = sq; }
    __syncthreads();
    if (tid < 8) {
        float a1 = rs[tid], a2 = rq[tid];
#pragma unroll
        for (int o = 4; o; o >>= 1) {
            a1 += __shfl_xor_sync(0xffu, a1, o);
            a2 += __shfl_xor_sync(0xffu, a2, o);
        }
        if (tid == 0) { rs[0] = a1; rq[0] = a2; }
    }
    __syncthreads();
    float mu = rs[0] * (1.0f / Dm);
    float var = rq[0] * (1.0f / Dm) - mu * mu;
    float inv = rsqrtf(var + 1e-5f);
    float o0 = g[tid]       * (v0 - mu) * inv + be[tid];
    float o1 = g[tid + 256] * (v1 - mu) * inv + be[tid + 256];
    x[base + tid]        = o0;
    x[base + tid + 256]  = o1;
    xr[base + tid]       = to_tf32(o0);
    xr[base + tid + 256] = to_tf32(o1);
}

// ==================== host orchestration ====================
#define STG 3
static inline int smemBytes(int BM, int BN, int BK) {
    return STG * (BM * (BK + 4) + BK * (BN + 8)) * 4;
}

static void CVT(const float* in, float* out, ll n, cudaStream_t st) {
    int n4 = (int)(n / 4);
    int thr = (n4 + 3) / 4;
    cvt_k<<<(thr + 255) / 256, 256, 0, st>>>(in, out, n4);
}

template<bool RELU, bool ROUND>
static void NN_big(const float* A, const float* B, float* C, const float* bias,
                   int M, int N, int K) {
    dim3 grid(N / 128, M / 128, 1);
    int sb = smemBytes(128, 128, 32);
    cudaFuncSetAttribute((const void*)gemm_tc<128, 128, 32, 2, 4, 256, STG, RELU, ROUND>,
                         cudaFuncAttributeMaxDynamicSharedMemorySize, sb);
    gemm_tc<128, 128, 32, 2, 4, 256, STG, RELU, ROUND><<<grid, 256, sb>>>(
        A, nullptr, B, C, bias, K, K, N, N, 0, 0, 0, 0, 0);
}

static void NN_512_split(const float* A, const float* B, float* Cpart,
                         const float* bias, int K, int nsplit) {
    int Ksl = K / nsplit;
    dim3 grid(Dm / 64, NTOK / 64, nsplit);
    int sb = smemBytes(64, 64, 32);
    cudaFuncSetAttribute((const void*)gemm_tc<64, 64, 32, 2, 2, 128, STG, false, false>,
                         cudaFuncAttributeMaxDynamicSharedMemorySize, sb);
    gemm_tc<64, 64, 32, 2, 2, 128, STG, false, false><<<grid, 128, sb>>>(
        A, nullptr, B, Cpart, bias, Ksl, K, Dm, Dm,
        (ll)Ksl, (ll)Ksl * Dm, (ll)NTOK * Dm, 0, 1);
}

static void QKV(const float* xq, const float* xkv, const float* w4, const float* b4,
                float* qkv) {
    dim3 grid(Dm / 64, NTOK / 64, 3);
    int sb = smemBytes(64, 64, 32);
    cudaFuncSetAttribute((const void*)gemm_tc<64, 64, 32, 2, 2, 128, STG, false, true>,
                         cudaFuncAttributeMaxDynamicSharedMemorySize, sb);
    gemm_tc<64, 64, 32, 2, 2, 128, STG, false, true><<<grid, 128, sb>>>(
        xq, xkv, w4, qkv, b4, Dm, Dm, Dm, Dm,
        0, (ll)Dm * Dm, (ll)NTOK * Dm, Dm, 0);
}

static const int FA_SMEM = (6 * FA_TILE + 64) * 4;
static const ll PSTRIDE = (ll)NTOK * Dm;

extern "C" void kernel_launch(void* const* d_in, const int* in_sizes, int n_in,
                              void* d_out, int out_size) {
    const int*   src        = (const int*)  d_in[0];
    const int*   tgt        = (const int*)  d_in[1];
    const float* enc_emb    = (const float*)d_in[2];
    const float* dec_emb    = (const float*)d_in[3];
    const float* pe         = (const float*)d_in[4];
    const float* enc_attn_w = (const float*)d_in[5];
    const float* enc_attn_b = (const float*)d_in[6];
    const float* enc_ffn_w1 = (const float*)d_in[7];
    const float* enc_ffn_b1 = (const float*)d_in[8];
    const float* enc_ffn_w2 = (const float*)d_in[9];
    const float* enc_ffn_b2 = (const float*)d_in[10];
    const float* enc_ln_g   = (const float*)d_in[11];
    const float* enc_ln_b   = (const float*)d_in[12];
    const float* dec_sa_w   = (const float*)d_in[13];
    const float* dec_sa_b   = (const float*)d_in[14];
    const float* dec_ca_w   = (const float*)d_in[15];
    const float* dec_ca_b   = (const float*)d_in[16];
    const float* dec_ffn_w1 = (const float*)d_in[17];
    const float* dec_ffn_b1 = (const float*)d_in[18];
    const float* dec_ffn_w2 = (const float*)d_in[19];
    const float* dec_ffn_b2 = (const float*)d_in[20];
    const float* dec_ln_g   = (const float*)d_in[21];
    const float* dec_ln_b   = (const float*)d_in[22];
    const float* out_w      = (const float*)d_in[23];
    const float* out_b      = (const float*)d_in[24];

    cudaFuncSetAttribute(flash_k, cudaFuncAttributeMaxDynamicSharedMemorySize, FA_SMEM);

    float *px, *py, *pxr, *pyr, *pqkv, *pctx, *ppart, *pffn;
    float *wEA, *wEF1, *wEF2, *wDS, *wDC, *wDF1, *wDF2, *wO;
    cudaGetSymbolAddress((void**)&px,    g_x);
    cudaGetSymbolAddress((void**)&py,    g_y);
    cudaGetSymbolAddress((void**)&pxr,   g_xr);
    cudaGetSymbolAddress((void**)&pyr,   g_yr);
    cudaGetSymbolAddress((void**)&pqkv,  g_qkv);
    cudaGetSymbolAddress((void**)&pctx,  g_ctx);
    cudaGetSymbolAddress((void**)&ppart, g_part);
    cudaGetSymbolAddress((void**)&pffn,  g_ffn);
    cudaGetSymbolAddress((void**)&wEA,   g_wEA);
    cudaGetSymbolAddress((void**)&wEF1,  g_wEF1);
    cudaGetSymbolAddress((void**)&wEF2,  g_wEF2);
    cudaGetSymbolAddress((void**)&wDS,   g_wDS);
    cudaGetSymbolAddress((void**)&wDC,   g_wDC);
    cudaGetSymbolAddress((void**)&wDF1,  g_wDF1);
    cudaGetSymbolAddress((void**)&wDF2,  g_wDF2);
    cudaGetSymbolAddress((void**)&wO,    g_wO);

    // -------- side stream: weight pre-rounding overlaps main compute --------
    // (created during capture; the captured graph records the DAG. Objects are
    //  intentionally not destroyed — host-side only, a few per capture.)
    cudaStream_t s2;
    cudaStreamCreateWithFlags(&s2, cudaStreamNonBlocking);
    cudaEvent_t evFork, evEA, evEncW, evDecW, evWO;
    cudaEventCreateWithFlags(&evFork, cudaEventDisableTiming);
    cudaEventCreateWithFlags(&evEA,   cudaEventDisableTiming);
    cudaEventCreateWithFlags(&evEncW, cudaEventDisableTiming);
    cudaEventCreateWithFlags(&evDecW, cudaEventDisableTiming);
    cudaEventCreateWithFlags(&evWO,   cudaEventDisableTiming);

    cudaEventRecord(evFork, 0);
    cudaStreamWaitEvent(s2, evFork, 0);
    CVT(enc_attn_w, wEA,  (ll)LEn * 4 * Dm * Dm, s2);
    cudaEventRecord(evEA, s2);
    CVT(enc_ffn_w1, wEF1, (ll)LEn * Dm * DFFn, s2);
    CVT(enc_ffn_w2, wEF2, (ll)LEn * DFFn * Dm, s2);
    cudaEventRecord(evEncW, s2);
    CVT(dec_sa_w,   wDS,  (ll)LDn * 4 * Dm * Dm, s2);
    CVT(dec_ca_w,   wDC,  (ll)LDn * 4 * Dm * Dm, s2);
    CVT(dec_ffn_w1, wDF1, (ll)LDn * Dm * DFFn, s2);
    CVT(dec_ffn_w2, wDF2, (ll)LDn * DFFn * Dm, s2);
    cudaEventRecord(evDecW, s2);
    CVT(out_w,      wO,   (ll)Dm * Vn, s2);
    cudaEventRecord(evWO, s2);

    float* pq = pqkv;
    float* pk = pqkv + PSTRIDE;
    float* pv = pqkv + 2 * PSTRIDE;

    // -------- encoder --------
    embed_k<<<NTOK, 256>>>(px, pxr, enc_emb, src, pe);
    cudaStreamWaitEvent(0, evEA, 0);
    for (int i = 0; i < LEn; i++) {
        const float* w4 = wEA + (ll)i * 4 * Dm * Dm;
        const float* b4 = enc_attn_b + (ll)i * 4 * Dm;
        QKV(pxr, pxr, w4, b4, pqkv);
        dim3 fg(Sn / 64, Hn, Bn);
        flash_k<<<fg, 128, FA_SMEM>>>(pq, pk, pv, pctx, src, 0);
        NN_512_split(pctx, w4 + 3 * Dm * Dm, ppart, b4 + 3 * Dm, Dm, 2);
        ln_res_k<<<NTOK, 256>>>(px, pxr, ppart, 2, PSTRIDE,
                                enc_ln_g + (i * 2 + 0) * Dm, enc_ln_b + (i * 2 + 0) * Dm);
        if (i == 0) cudaStreamWaitEvent(0, evEncW, 0);
        NN_big<true, true>(pxr, wEF1 + (ll)i * Dm * DFFn, pffn,
                           enc_ffn_b1 + i * DFFn, NTOK, DFFn, Dm);
        NN_512_split(pffn, wEF2 + (ll)i * DFFn * Dm, ppart, enc_ffn_b2 + i * Dm,
                     DFFn, 4);
        ln_res_k<<<NTOK, 256>>>(px, pxr, ppart, 4, PSTRIDE,
                                enc_ln_g + (i * 2 + 1) * Dm, enc_ln_b + (i * 2 + 1) * Dm);
    }

    // -------- decoder --------
    embed_k<<<NTOK, 256>>>(py, pyr, dec_emb, tgt, pe);
    cudaStreamWaitEvent(0, evDecW, 0);
    for (int i = 0; i < LDn; i++) {
        const float* sw4 = wDS + (ll)i * 4 * Dm * Dm;
        const float* sb4 = dec_sa_b + (ll)i * 4 * Dm;
        QKV(pyr, pyr, sw4, sb4, pqkv);
        dim3 fgc(Sn / 64 + 1, Hn, Bn);   // +1 q-tile slot = masked-row fixup blocks
        flash_k<<<fgc, 128, FA_SMEM>>>(pq, pk, pv, pctx, tgt, 1);
        NN_512_split(pctx, sw4 + 3 * Dm * Dm, ppart, sb4 + 3 * Dm, Dm, 2);
        ln_res_k<<<NTOK, 256>>>(py, pyr, ppart, 2, PSTRIDE,
                                dec_ln_g + (i * 3 + 0) * Dm, dec_ln_b + (i * 3 + 0) * Dm);

        const float* cw4 = wDC + (ll)i * 4 * Dm * Dm;
        const float* cb4 = dec_ca_b + (ll)i * 4 * Dm;
        QKV(pyr, pxr, cw4, cb4, pqkv);
        dim3 fg(Sn / 64, Hn, Bn);
        flash_k<<<fg, 128, FA_SMEM>>>(pq, pk, pv, pctx, src, 0);
        NN_512_split(pctx, cw4 + 3 * Dm * Dm, ppart, cb4 + 3 * Dm, Dm, 2);
        ln_res_k<<<NTOK, 256>>>(py, pyr, ppart, 2, PSTRIDE,
                                dec_ln_g + (i * 3 + 1) * Dm, dec_ln_b + (i * 3 + 1) * Dm);

        NN_big<true, true>(pyr, wDF1 + (ll)i * Dm * DFFn, pffn,
                           dec_ffn_b1 + i * DFFn, NTOK, DFFn, Dm);
        NN_512_split(pffn, wDF2 + (ll)i * DFFn * Dm, ppart, dec_ffn_b2 + i * Dm,
                     DFFn, 4);
        ln_res_k<<<NTOK, 256>>>(py, pyr, ppart, 4, PSTRIDE,
                                dec_ln_g + (i * 3 + 2) * Dm, dec_ln_b + (i * 3 + 2) * Dm);
    }

    // -------- final projection --------
    cudaStreamWaitEvent(0, evWO, 0);
    NN_big<false, false>(pyr, wO, (float*)d_out, out_b, NTOK, Vn, Dm);
}

// round 15
// speedup vs baseline: 1.0464x; 1.0111x over previous
#include <cuda_runtime.h>
#include <math.h>

// Problem constants
#define Dm   512
#define Hn   8
#define DKn  64
#define Sn   512
#define Bn   4
#define NTOK 2048      // B * S
#define DFFn 2048
#define Vn   32000
#define LEn  6
#define LDn  6

typedef long long ll;

// -------------------- scratch (device globals; no allocation) --------------------
__device__ float g_x   [NTOK * Dm];       // fp32 residual stream (encoder)
__device__ float g_y   [NTOK * Dm];       // fp32 residual stream (decoder)
__device__ float g_xr  [NTOK * Dm];       // tf32-rounded copy of g_x
__device__ float g_yr  [NTOK * Dm];       // tf32-rounded copy of g_y
__device__ float g_qkv [3 * NTOK * Dm];   // rounded
__device__ float g_ctx [NTOK * Dm];       // rounded (flash epilogue)
__device__ float g_part[4 * NTOK * Dm];   // split-K partials (raw fp32)
__device__ float g_ffn [NTOK * DFFn];     // rounded (ffn1 epilogue)

// tf32-rounded weight copies
__device__ float g_wEA [LEn * 4 * Dm * Dm];
__device__ float g_wEF1[LEn * Dm * DFFn];
__device__ float g_wEF2[LEn * DFFn * Dm];
__device__ float g_wDS [LDn * 4 * Dm * Dm];
__device__ float g_wDC [LDn * 4 * Dm * Dm];
__device__ float g_wDF1[LDn * Dm * DFFn];
__device__ float g_wDF2[LDn * DFFn * Dm];
__device__ float g_wO  [Dm * Vn];

// -------------------- helpers --------------------
__device__ __forceinline__ float to_tf32(float x) {
    float y;
    asm("cvt.rna.tf32.f32 %0, %1;" : "=f"(y) : "f"(x));
    return y;
}

__device__ __forceinline__ void mma_tf32(float* d, const unsigned* a, const unsigned* b) {
    asm volatile(
        "mma.sync.aligned.m16n8k8.row.col.f32.tf32.tf32.f32 "
        "{%0,%1,%2,%3}, {%4,%5,%6,%7}, {%8,%9}, {%0,%1,%2,%3};\n"
        : "+f"(d[0]), "+f"(d[1]), "+f"(d[2]), "+f"(d[3])
        : "r"(a[0]), "r"(a[1]), "r"(a[2]), "r"(a[3]), "r"(b[0]), "r"(b[1]));
}

__device__ __forceinline__ unsigned su32(const void* p) {
    return (unsigned)__cvta_generic_to_shared(p);
}
#define CP_ASYNC16(s, g) \
    asm volatile("cp.async.cg.shared.global [%0], [%1], 16;\n" :: "r"(s), "l"(g))
#define CP_COMMIT() asm volatile("cp.async.commit_group;\n" ::: "memory")

// -------------------- tf32 pre-round (weights) --------------------
__global__ void cvt_k(const float* __restrict__ in, float* __restrict__ out, int n4) {
    int i = blockIdx.x * 256 + threadIdx.x;
    if (i < n4) {
        float4 v = ((const float4*)in)[i];
        v.x = to_tf32(v.x); v.y = to_tf32(v.y);
        v.z = to_tf32(v.z); v.w = to_tf32(v.w);
        ((float4*)out)[i] = v;
    }
}

// ==================== TF32 multistage tensor-core GEMM ====================
// All operands pre-rounded to tf32. No cvt in the inner loop.
template<int BM, int BN, int BK, int WGM, int WGN, int NTH, int STAGES, bool RELU, bool ROUND>
__global__ void __launch_bounds__(NTH)
gemm_tc(const float* __restrict__ A, const float* __restrict__ Aalt,
        const float* __restrict__ B, float* __restrict__ C,
        const float* __restrict__ bias,
        int K, int lda, int ldb, int ldc,
        ll sAz, ll sBz, ll sCz, int biasStride, int biasZ0) {
    const int z = blockIdx.z;
    if (Aalt != nullptr && z > 0) A = Aalt;
    A += (ll)z * sAz;
    B += (ll)z * sBz;
    C += (ll)z * sCz;
    if (bias) {
        if (biasZ0 && z > 0) bias = nullptr;
        else bias += (ll)z * biasStride;
    }

    const int tid = threadIdx.x;
    const int lane = tid & 31, warp = tid >> 5;
    const int wm = warp / WGN, wn = warp % WGN;
    constexpr int WTM = BM / WGM, WTN = BN / WGN;
    constexpr int MT = WTM / 16, NT = WTN / 8;
    const int row0 = blockIdx.y * BM, col0 = blockIdx.x * BN;
    const int g = lane >> 2, tg = lane & 3;

    extern __shared__ float smem[];
    constexpr int AL = BK + 4;
    constexpr int BL = BN + 8;
    constexpr int ASZ = BM * AL;
    constexpr int BSZ = BK * BL;
    float* Asm = smem;
    float* Bsm = smem + STAGES * ASZ;

    constexpr int CA = BM * BK / (4 * NTH);
    constexpr int CB = BK * BN / (4 * NTH);

    auto issue = [&](int it, int st) {
        const int k0 = it * BK;
        float* as = Asm + st * ASZ;
        float* bs = Bsm + st * BSZ;
#pragma unroll
        for (int i = 0; i < CA; i++) {
            int t = tid + i * NTH;
            int r = t / (BK / 4), kq = (t % (BK / 4)) * 4;
            CP_ASYNC16(su32(as + r * AL + kq), A + (ll)(row0 + r) * lda + k0 + kq);
        }
#pragma unroll
        for (int i = 0; i < CB; i++) {
            int t = tid + i * NTH;
            int r = t / (BN / 4), nq = (t % (BN / 4)) * 4;
            CP_ASYNC16(su32(bs + r * BL + nq), B + (ll)(k0 + r) * ldb + col0 + nq);
        }
        CP_COMMIT();
    };

    float acc[MT][NT][4] = {};
    const int nIt = K / BK;

#pragma unroll
    for (int s = 0; s < STAGES - 1; s++)
        if (s < nIt) issue(s, s);

    for (int it = 0; it < nIt; it++) {
        asm volatile("cp.async.wait_group %0;\n" :: "n"(STAGES - 2) : "memory");
        __syncthreads();
        const int pre = it + STAGES - 1;
        if (pre < nIt) issue(pre, pre % STAGES);
        else CP_COMMIT();

        const float* as = Asm + (it % STAGES) * ASZ;
        const float* bs = Bsm + (it % STAGES) * BSZ;

#pragma unroll
        for (int ks = 0; ks < BK / 8; ks++) {
            const int kb = ks * 8;
            unsigned af[MT][4], bf[NT][2];
#pragma unroll
            for (int mt = 0; mt < MT; mt++) {
                int r = wm * WTM + mt * 16 + g;
                af[mt][0] = __float_as_uint(as[r * AL + kb + tg]);
                af[mt][1] = __float_as_uint(as[(r + 8) * AL + kb + tg]);
                af[mt][2] = __float_as_uint(as[r * AL + kb + tg + 4]);
                af[mt][3] = __float_as_uint(as[(r + 8) * AL + kb + tg + 4]);
            }
#pragma unroll
            for (int nt = 0; nt < NT; nt++) {
                int c = wn * WTN + nt * 8 + g;
                bf[nt][0] = __float_as_uint(bs[(kb + tg) * BL + c]);
                bf[nt][1] = __float_as_uint(bs[(kb + tg + 4) * BL + c]);
            }
#pragma unroll
            for (int mt = 0; mt < MT; mt++)
#pragma unroll
                for (int nt = 0; nt < NT; nt++)
                    mma_tf32(acc[mt][nt], af[mt], bf[nt]);
        }
    }

#pragma unroll
    for (int mt = 0; mt < MT; mt++) {
#pragma unroll
        for (int nt = 0; nt < NT; nt++) {
            int r = row0 + wm * WTM + mt * 16 + g;
            int c = col0 + wn * WTN + nt * 8 + tg * 2;
            float b0 = 0.f, b1 = 0.f;
            if (bias) { b0 = bias[c]; b1 = bias[c + 1]; }
            float2 v0, v1;
            v0.x = acc[mt][nt][0] + b0; v0.y = acc[mt][nt][1] + b1;
            v1.x = acc[mt][nt][2] + b0; v1.y = acc[mt][nt][3] + b1;
            if (RELU) {
                v0.x = fmaxf(v0.x, 0.f); v0.y = fmaxf(v0.y, 0.f);
                v1.x = fmaxf(v1.x, 0.f); v1.y = fmaxf(v1.y, 0.f);
            }
            if (ROUND) {
                v0.x = to_tf32(v0.x); v0.y = to_tf32(v0.y);
                v1.x = to_tf32(v1.x); v1.y = to_tf32(v1.y);
            }
            *(float2*)(C + (ll)r * ldc + c) = v0;
            *(float2*)(C + (ll)(r + 8) * ldc + c) = v1;
        }
    }
}

// ==================== fused flash attention (R8-proven structure) ====================
// Q/K/V pre-rounded. K+V double-buffered via cp.async (one group per tile).
// All 8 k-tiles processed; masking matches reference semantics exactly
// (fully-masked rows -> uniform softmax over all 512 keys).
#define FA_STRIDE 68
#define FA_TILE (64 * FA_STRIDE)
__global__ void __launch_bounds__(128)
flash_k(const float* __restrict__ Q, const float* __restrict__ Kv,
        const float* __restrict__ Vv, float* __restrict__ ctx,
        const int* __restrict__ tok, int causal) {
    extern __shared__ float sm[];
    float* Qs = sm;
    float* Ks = sm + FA_TILE;
    float* Vs = sm + 3 * FA_TILE;
    float* Ps = sm + 5 * FA_TILE;
    int* kmv = (int*)(sm + 6 * FA_TILE);

    const int qt = blockIdx.x, h = blockIdx.y, b = blockIdx.z;
    const int tid = threadIdx.x, lane = tid & 31, w = tid >> 5;
    const int g = lane >> 2, tg = lane & 3;
    const int wrow = w * 16;

    const ll base = (ll)(b * Sn) * Dm + h * DKn;
    const int kp = tid >> 1, half = (tid & 1) * 32;

    auto issueKV = [&](int kt, int buf) {
        const float* ksrc = Kv + base + (ll)(kt * 64 + kp) * Dm + half;
        const float* vsrc = Vv + base + (ll)(kt * 64 + kp) * Dm + half;
        unsigned kdst = su32(Ks + buf * FA_TILE + kp * FA_STRIDE + half);
        unsigned vdst = su32(Vs + buf * FA_TILE + kp * FA_STRIDE + half);
#pragma unroll
        for (int j = 0; j < 32; j += 4) {
            CP_ASYNC16(kdst + j * 4, ksrc + j);
            CP_ASYNC16(vdst + j * 4, vsrc + j);
        }
        CP_COMMIT();
    };

    issueKV(0, 0);

    {   // Q already tf32 — straight copy
        const float* src = Q + base + (ll)(qt * 64 + kp) * Dm + half;
        float* dst = Qs + kp * FA_STRIDE + half;
#pragma unroll
        for (int j = 0; j < 32; j += 4)
            *(float4*)(dst + j) = *(const float4*)(src + j);
    }

    const int qrow0 = qt * 64 + wrow + g, qrow1 = qrow0 + 8;
    bool qv0 = true, qv1 = true;
    if (causal) { qv0 = tok[b * Sn + qrow0] != 0; qv1 = tok[b * Sn + qrow1] != 0; }

    float m0 = -1e30f, m1 = -1e30f, l0 = 0.f, l1 = 0.f;
    float acc_o[8][4] = {};

    for (int kt = 0; kt < 8; kt++) {
        const int buf = kt & 1;
        if (!causal && tid < 64) kmv[tid] = tok[b * Sn + kt * 64 + tid];
        if (kt < 7) {
            issueKV(kt + 1, buf ^ 1);
            asm volatile("cp.async.wait_group 1;\n" ::: "memory");
        } else {
            asm volatile("cp.async.wait_group 0;\n" ::: "memory");
        }
        __syncthreads();

        const float* Kb = Ks + buf * FA_TILE;
        const float* Vb = Vs + buf * FA_TILE;

        float s[8][4] = {};
#pragma unroll
        for (int kc = 0; kc < 8; kc++) {
            const int kb = kc * 8;
            unsigned af[4];
            af[0] = __float_as_uint(Qs[(wrow + g) * FA_STRIDE + kb + tg]);
            af[1] = __float_as_uint(Qs[(wrow + g + 8) * FA_STRIDE + kb + tg]);
            af[2] = __float_as_uint(Qs[(wrow + g) * FA_STRIDE + kb + tg + 4]);
            af[3] = __float_as_uint(Qs[(wrow + g + 8) * FA_STRIDE + kb + tg + 4]);
#pragma unroll
            for (int nt = 0; nt < 8; nt++) {
                unsigned bf[2];
                bf[0] = __float_as_uint(Kb[(nt * 8 + g) * FA_STRIDE + kb + tg]);
                bf[1] = __float_as_uint(Kb[(nt * 8 + g) * FA_STRIDE + kb + tg + 4]);
                mma_tf32(s[nt], af, bf);
            }
        }

        float vmax0 = -1e30f, vmax1 = -1e30f;
#pragma unroll
        for (int nt = 0; nt < 8; nt++) {
#pragma unroll
            for (int jj = 0; jj < 2; jj++) {
                int ncol = nt * 8 + tg * 2 + jj;
                int kcol = kt * 64 + ncol;
                bool mk0, mk1;
                if (causal) { mk0 = qv0 && (kcol <= qrow0); mk1 = qv1 && (kcol <= qrow1); }
                else        { bool km = kmv[ncol] != 0; mk0 = km; mk1 = km; }
                float v0 = mk0 ? s[nt][jj] * 0.125f : -1e9f;
                float v1 = mk1 ? s[nt][2 + jj] * 0.125f : -1e9f;
                s[nt][jj] = v0; s[nt][2 + jj] = v1;
                vmax0 = fmaxf(vmax0, v0); vmax1 = fmaxf(vmax1, v1);
            }
        }
        vmax0 = fmaxf(vmax0, __shfl_xor_sync(0xffffffffu, vmax0, 1));
        vmax0 = fmaxf(vmax0, __shfl_xor_sync(0xffffffffu, vmax0, 2));
        vmax1 = fmaxf(vmax1, __shfl_xor_sync(0xffffffffu, vmax1, 1));
        vmax1 = fmaxf(vmax1, __shfl_xor_sync(0xffffffffu, vmax1, 2));

        float mn0 = fmaxf(m0, vmax0), mn1 = fmaxf(m1, vmax1);
        float a0 = __expf(m0 - mn0), a1 = __expf(m1 - mn1);
        m0 = mn0; m1 = mn1;

        float rs0 = 0.f, rs1 = 0.f;
#pragma unroll
        for (int nt = 0; nt < 8; nt++) {
#pragma unroll
            for (int jj = 0; jj < 2; jj++) {
                int ncol = nt * 8 + tg * 2 + jj;
                float p0 = __expf(s[nt][jj] - mn0);
                float p1 = __expf(s[nt][2 + jj] - mn1);
                rs0 += p0; rs1 += p1;
                Ps[(wrow + g) * FA_STRIDE + ncol] = to_tf32(p0);
                Ps[(wrow + g + 8) * FA_STRIDE + ncol] = to_tf32(p1);
            }
        }
        rs0 += __shfl_xor_sync(0xffffffffu, rs0, 1);
        rs0 += __shfl_xor_sync(0xffffffffu, rs0, 2);
        rs1 += __shfl_xor_sync(0xffffffffu, rs1, 1);
        rs1 += __shfl_xor_sync(0xffffffffu, rs1, 2);
        l0 = l0 * a0 + rs0; l1 = l1 * a1 + rs1;
#pragma unroll
        for (int nt = 0; nt < 8; nt++) {
            acc_o[nt][0] *= a0; acc_o[nt][1] *= a0;
            acc_o[nt][2] *= a1; acc_o[nt][3] *= a1;
        }
        __syncwarp();

#pragma unroll
        for (int kc = 0; kc < 8; kc++) {
            const int kb = kc * 8;
            unsigned af[4];
            af[0] = __float_as_uint(Ps[(wrow + g) * FA_STRIDE + kb + tg]);
            af[1] = __float_as_uint(Ps[(wrow + g + 8) * FA_STRIDE + kb + tg]);
            af[2] = __float_as_uint(Ps[(wrow + g) * FA_STRIDE + kb + tg + 4]);
            af[3] = __float_as_uint(Ps[(wrow + g + 8) * FA_STRIDE + kb + tg + 4]);
#pragma unroll
            for (int nt = 0; nt < 8; nt++) {
                unsigned bf[2];
                bf[0] = __float_as_uint(Vb[(kb + tg) * FA_STRIDE + nt * 8 + g]);
                bf[1] = __float_as_uint(Vb[(kb + tg + 4) * FA_STRIDE + nt * 8 + g]);
                mma_tf32(acc_o[nt], af, bf);
            }
        }
        __syncthreads();
    }

    float inv0 = 1.f / l0, inv1 = 1.f / l1;
#pragma unroll
    for (int nt = 0; nt < 8; nt++) {
        int c = nt * 8 + tg * 2;
        float2 o0, o1;
        o0.x = to_tf32(acc_o[nt][0] * inv0); o0.y = to_tf32(acc_o[nt][1] * inv0);
        o1.x = to_tf32(acc_o[nt][2] * inv1); o1.y = to_tf32(acc_o[nt][3] * inv1);
        *(float2*)(ctx + base + (ll)qrow0 * Dm + c) = o0;
        *(float2*)(ctx + base + (ll)qrow1 * Dm + c) = o1;
    }
}

// -------------------- embedding + PE (dual write: fp32 + tf32) --------------------
__global__ void embed_k(float* __restrict__ out, float* __restrict__ outr,
                        const float* __restrict__ emb,
                        const int* __restrict__ tok, const float* __restrict__ pe) {
    int t = blockIdx.x;
    int s = t & (Sn - 1);
    int tk = tok[t];
    const float scale = 22.627416997969522f;
    int base = t * Dm;
    for (int d = threadIdx.x; d < Dm; d += blockDim.x) {
        float v = emb[tk * Dm + d] * scale + pe[s * Dm + d];
        out[base + d] = v;
        outr[base + d] = to_tf32(v);
    }
}

// -------------------- residual + split-K reduce + LayerNorm (dual write) --------------------
__global__ void ln_res_k(float* __restrict__ x, float* __restrict__ xr,
                         const float* __restrict__ parts, int npart, ll pstride,
                         const float* __restrict__ g, const float* __restrict__ be) {
    int r = blockIdx.x;
    int base = r * Dm;
    int tid = threadIdx.x;
    float v0 = x[base + tid];
    float v1 = x[base + tid + 256];
    for (int p = 0; p < npart; p++) {
        v0 += parts[p * pstride + base + tid];
        v1 += parts[p * pstride + base + tid + 256];
    }

    float s = v0 + v1;
    float sq = v0 * v0 + v1 * v1;
    __shared__ float rs[8], rq[8];
#pragma unroll
    for (int o = 16; o; o >>= 1) {
        s  += __shfl_xor_sync(0xffffffffu, s, o);
        sq += __shfl_xor_sync(0xffffffffu, sq, o);
    }
    if ((tid & 31) == 0) { rs[tid >> 5] = s; rq[tid >> 5] = sq; }
    __syncthreads();
    if (tid < 8) {
        float a1 = rs[tid], a2 = rq[tid];
#pragma unroll
        for (int o = 4; o; o >>= 1) {
            a1 += __shfl_xor_sync(0xffu, a1, o);
            a2 += __shfl_xor_sync(0xffu, a2, o);
        }
        if (tid == 0) { rs[0] = a1; rq[0] = a2; }
    }
    __syncthreads();
    float mu = rs[0] * (1.0f / Dm);
    float var = rq[0] * (1.0f / Dm) - mu * mu;
    float inv = rsqrtf(var + 1e-5f);
    float o0 = g[tid]       * (v0 - mu) * inv + be[tid];
    float o1 = g[tid + 256] * (v1 - mu) * inv + be[tid + 256];
    x[base + tid]        = o0;
    x[base + tid + 256]  = o1;
    xr[base + tid]       = to_tf32(o0);
    xr[base + tid + 256] = to_tf32(o1);
}

// ==================== host orchestration ====================
#define STG 3
static inline int smemBytes(int BM, int BN, int BK) {
    return STG * (BM * (BK + 4) + BK * (BN + 8)) * 4;
}

static void CVT(const float* in, float* out, ll n, cudaStream_t st) {
    int n4 = (int)(n / 4);
    cvt_k<<<(n4 + 255) / 256, 256, 0, st>>>(in, out, n4);
}

template<bool RELU, bool ROUND>
static void NN_big(const float* A, const float* B, float* C, const float* bias,
                   int M, int N, int K) {
    dim3 grid(N / 128, M / 128, 1);
    int sb = smemBytes(128, 128, 32);
    cudaFuncSetAttribute((const void*)gemm_tc<128, 128, 32, 2, 4, 256, STG, RELU, ROUND>,
                         cudaFuncAttributeMaxDynamicSharedMemorySize, sb);
    gemm_tc<128, 128, 32, 2, 4, 256, STG, RELU, ROUND><<<grid, 256, sb>>>(
        A, nullptr, B, C, bias, K, K, N, N, 0, 0, 0, 0, 0);
}

static void NN_512_split(const float* A, const float* B, float* Cpart,
                         const float* bias, int K, int nsplit) {
    int Ksl = K / nsplit;
    dim3 grid(Dm / 64, NTOK / 64, nsplit);
    int sb = smemBytes(64, 64, 32);
    cudaFuncSetAttribute((const void*)gemm_tc<64, 64, 32, 2, 2, 128, STG, false, false>,
                         cudaFuncAttributeMaxDynamicSharedMemorySize, sb);
    gemm_tc<64, 64, 32, 2, 2, 128, STG, false, false><<<grid, 128, sb>>>(
        A, nullptr, B, Cpart, bias, Ksl, K, Dm, Dm,
        (ll)Ksl, (ll)Ksl * Dm, (ll)NTOK * Dm, 0, 1);
}

static void QKV(const float* xq, const float* xkv, const float* w4, const float* b4,
                float* qkv) {
    dim3 grid(Dm / 64, NTOK / 64, 3);
    int sb = smemBytes(64, 64, 32);
    cudaFuncSetAttribute((const void*)gemm_tc<64, 64, 32, 2, 2, 128, STG, false, true>,
                         cudaFuncAttributeMaxDynamicSharedMemorySize, sb);
    gemm_tc<64, 64, 32, 2, 2, 128, STG, false, true><<<grid, 128, sb>>>(
        xq, xkv, w4, qkv, b4, Dm, Dm, Dm, Dm,
        0, (ll)Dm * Dm, (ll)NTOK * Dm, Dm, 0);
}

static const int FA_SMEM = (6 * FA_TILE + 64) * 4;
static const ll PSTRIDE = (ll)NTOK * Dm;

extern "C" void kernel_launch(void* const* d_in, const int* in_sizes, int n_in,
                              void* d_out, int out_size) {
    const int*   src        = (const int*)  d_in[0];
    const int*   tgt        = (const int*)  d_in[1];
    const float* enc_emb    = (const float*)d_in[2];
    const float* dec_emb    = (const float*)d_in[3];
    const float* pe         = (const float*)d_in[4];
    const float* enc_attn_w = (const float*)d_in[5];
    const float* enc_attn_b = (const float*)d_in[6];
    const float* enc_ffn_w1 = (const float*)d_in[7];
    const float* enc_ffn_b1 = (const float*)d_in[8];
    const float* enc_ffn_w2 = (const float*)d_in[9];
    const float* enc_ffn_b2 = (const float*)d_in[10];
    const float* enc_ln_g   = (const float*)d_in[11];
    const float* enc_ln_b   = (const float*)d_in[12];
    const float* dec_sa_w   = (const float*)d_in[13];
    const float* dec_sa_b   = (const float*)d_in[14];
    const float* dec_ca_w   = (const float*)d_in[15];
    const float* dec_ca_b   = (const float*)d_in[16];
    const float* dec_ffn_w1 = (const float*)d_in[17];
    const float* dec_ffn_b1 = (const float*)d_in[18];
    const float* dec_ffn_w2 = (const float*)d_in[19];
    const float* dec_ffn_b2 = (const float*)d_in[20];
    const float* dec_ln_g   = (const float*)d_in[21];
    const float* dec_ln_b   = (const float*)d_in[22];
    const float* out_w      = (const float*)d_in[23];
    const float* out_b      = (const float*)d_in[24];

    cudaFuncSetAttribute(flash_k, cudaFuncAttributeMaxDynamicSharedMemorySize, FA_SMEM);

    float *px, *py, *pxr, *pyr, *pqkv, *pctx, *ppart, *pffn;
    float *wEA, *wEF1, *wEF2, *wDS, *wDC, *wDF1, *wDF2, *wO;
    cudaGetSymbolAddress((void**)&px,    g_x);
    cudaGetSymbolAddress((void**)&py,    g_y);
    cudaGetSymbolAddress((void**)&pxr,   g_xr);
    cudaGetSymbolAddress((void**)&pyr,   g_yr);
    cudaGetSymbolAddress((void**)&pqkv,  g_qkv);
    cudaGetSymbolAddress((void**)&pctx,  g_ctx);
    cudaGetSymbolAddress((void**)&ppart, g_part);
    cudaGetSymbolAddress((void**)&pffn,  g_ffn);
    cudaGetSymbolAddress((void**)&wEA,   g_wEA);
    cudaGetSymbolAddress((void**)&wEF1,  g_wEF1);
    cudaGetSymbolAddress((void**)&wEF2,  g_wEF2);
    cudaGetSymbolAddress((void**)&wDS,   g_wDS);
    cudaGetSymbolAddress((void**)&wDC,   g_wDC);
    cudaGetSymbolAddress((void**)&wDF1,  g_wDF1);
    cudaGetSymbolAddress((void**)&wDF2,  g_wDF2);
    cudaGetSymbolAddress((void**)&wO,    g_wO);

    // -------- side stream: weight pre-rounding overlaps main compute --------
    cudaStream_t s2;
    cudaStreamCreateWithFlags(&s2, cudaStreamNonBlocking);
    cudaEvent_t evFork, evEA, evEncW, evDecW, evWO;
    cudaEventCreateWithFlags(&evFork, cudaEventDisableTiming);
    cudaEventCreateWithFlags(&evEA,   cudaEventDisableTiming);
    cudaEventCreateWithFlags(&evEncW, cudaEventDisableTiming);
    cudaEventCreateWithFlags(&evDecW, cudaEventDisableTiming);
    cudaEventCreateWithFlags(&evWO,   cudaEventDisableTiming);

    cudaEventRecord(evFork, 0);
    cudaStreamWaitEvent(s2, evFork, 0);
    CVT(enc_attn_w, wEA,  (ll)LEn * 4 * Dm * Dm, s2);
    cudaEventRecord(evEA, s2);
    CVT(enc_ffn_w1, wEF1, (ll)LEn * Dm * DFFn, s2);
    CVT(enc_ffn_w2, wEF2, (ll)LEn * DFFn * Dm, s2);
    cudaEventRecord(evEncW, s2);
    CVT(dec_sa_w,   wDS,  (ll)LDn * 4 * Dm * Dm, s2);
    CVT(dec_ca_w,   wDC,  (ll)LDn * 4 * Dm * Dm, s2);
    CVT(dec_ffn_w1, wDF1, (ll)LDn * Dm * DFFn, s2);
    CVT(dec_ffn_w2, wDF2, (ll)LDn * DFFn * Dm, s2);
    cudaEventRecord(evDecW, s2);
    CVT(out_w,      wO,   (ll)Dm * Vn, s2);
    cudaEventRecord(evWO, s2);

    float* pq = pqkv;
    float* pk = pqkv + PSTRIDE;
    float* pv = pqkv + 2 * PSTRIDE;

    // -------- encoder --------
    embed_k<<<NTOK, 256>>>(px, pxr, enc_emb, src, pe);
    cudaStreamWaitEvent(0, evEA, 0);
    for (int i = 0; i < LEn; i++) {
        const float* w4 = wEA + (ll)i * 4 * Dm * Dm;
        const float* b4 = enc_attn_b + (ll)i * 4 * Dm;
        QKV(pxr, pxr, w4, b4, pqkv);
        dim3 fg(Sn / 64, Hn, Bn);
        flash_k<<<fg, 128, FA_SMEM>>>(pq, pk, pv, pctx, src, 0);
        NN_512_split(pctx, w4 + 3 * Dm * Dm, ppart, b4 + 3 * Dm, Dm, 4);
        ln_res_k<<<NTOK, 256>>>(px, pxr, ppart, 4, PSTRIDE,
                                enc_ln_g + (i * 2 + 0) * Dm, enc_ln_b + (i * 2 + 0) * Dm);
        if (i == 0) cudaStreamWaitEvent(0, evEncW, 0);
        NN_big<true, true>(pxr, wEF1 + (ll)i * Dm * DFFn, pffn,
                           enc_ffn_b1 + i * DFFn, NTOK, DFFn, Dm);
        NN_512_split(pffn, wEF2 + (ll)i * DFFn * Dm, ppart, enc_ffn_b2 + i * Dm,
                     DFFn, 4);
        ln_res_k<<<NTOK, 256>>>(px, pxr, ppart, 4, PSTRIDE,
                                enc_ln_g + (i * 2 + 1) * Dm, enc_ln_b + (i * 2 + 1) * Dm);
    }

    // -------- decoder --------
    embed_k<<<NTOK, 256>>>(py, pyr, dec_emb, tgt, pe);
    cudaStreamWaitEvent(0, evDecW, 0);
    for (int i = 0; i < LDn; i++) {
        const float* sw4 = wDS + (ll)i * 4 * Dm * Dm;
        const float* sb4 = dec_sa_b + (ll)i * 4 * Dm;
        QKV(pyr, pyr, sw4, sb4, pqkv);
        dim3 fg(Sn / 64, Hn, Bn);
        flash_k<<<fg, 128, FA_SMEM>>>(pq, pk, pv, pctx, tgt, 1);
        NN_512_split(pctx, sw4 + 3 * Dm * Dm, ppart, sb4 + 3 * Dm, Dm, 4);
        ln_res_k<<<NTOK, 256>>>(py, pyr, ppart, 4, PSTRIDE,
                                dec_ln_g + (i * 3 + 0) * Dm, dec_ln_b + (i * 3 + 0) * Dm);

        const float* cw4 = wDC + (ll)i * 4 * Dm * Dm;
        const float* cb4 = dec_ca_b + (ll)i * 4 * Dm;
        QKV(pyr, pxr, cw4, cb4, pqkv);
        flash_k<<<fg, 128, FA_SMEM>>>(pq, pk, pv, pctx, src, 0);
        NN_512_split(pctx, cw4 + 3 * Dm * Dm, ppart, cb4 + 3 * Dm, Dm, 4);
        ln_res_k<<<NTOK, 256>>>(py, pyr, ppart, 4, PSTRIDE,
                                dec_ln_g + (i * 3 + 1) * Dm, dec_ln_b + (i * 3 + 1) * Dm);

        NN_big<true, true>(pyr, wDF1 + (ll)i * Dm * DFFn, pffn,
                           dec_ffn_b1 + i * DFFn, NTOK, DFFn, Dm);
        NN_512_split(pffn, wDF2 + (ll)i * DFFn * Dm, ppart, dec_ffn_b2 + i * Dm,
                     DFFn, 4);
        ln_res_k<<<NTOK, 256>>>(py, pyr, ppart, 4, PSTRIDE,
                                dec_ln_g + (i * 3 + 2) * Dm, dec_ln_b + (i * 3 + 2) * Dm);
    }

    // -------- final projection --------
    cudaStreamWaitEvent(0, evWO, 0);
    NN_big<false, false>(pyr, wO, (float*)d_out, out_b, NTOK, Vn, Dm);
}